// round 9
// baseline (speedup 1.0000x reference)
#include <cuda_runtime.h>
#include <math.h>

// ---------------- Scratch (no runtime allocation allowed) ----------------
#define T_LEN 2048
#define D_COLS 2700
#define CH 128
#define WARM 128
#define NCHUNK (T_LEN / CH)         // 16
__device__ __align__(16) float g_tm[T_LEN * D_COLS];
__device__ float g_part[300 * NCHUNK];

__device__ __forceinline__ float sigmoidf(float x) {
    return 1.0f / (1.0f + expf(-x));
}

// =======================================================================
// Kernel 1: gathered GEMM via mma.sync bf16 3-term split + bias + sigmoid
//   C[m][n] = sigmoid( sum_k emb[doc[m]][k] * diags[n][k] + bias[n] )
//   M=2048, N=2700, K=300 (pad 304). CTA 128x128, BK=16, 19 stages.
//   8 warps (2m x 4n), warp tile 64x32 = 4x4 m16n8k16 fragments.
//   Producer splits f32 -> (bf16 hi, bf16 mid) ONCE into smem; consumer is
//   pure LDS.64 + HMMA. Terms: ah*bh + am*bh + ah*bm.
//   MMA schedule: term-major over mt-pairs -> same-acc reuse distance 8.
// =======================================================================
#define NKS 19
#define RSTRIDE 24                  // smem row stride in u32 (96B): LDS.64 conflict-free
#define BUFU32 (128 * RSTRIDE)      // 3072 u32 = 12288 B per operand buffer
#define SMEM_BYTES (4 * BUFU32 * 4) // 49152 (Ah0,Bh0,Ah1,Bh1) -- needs opt-in

// split x,y (k-even, k-odd) into packed bf16 hi-pair and mid-pair
__device__ __forceinline__ void bsplit2(float x, float y, unsigned& hp, unsigned& mp) {
    asm("cvt.rn.bf16x2.f32 %0, %1, %2;" : "=r"(hp) : "f"(y), "f"(x));
    float hx = __uint_as_float(hp << 16);
    float hy = __uint_as_float(hp & 0xFFFF0000u);
    asm("cvt.rn.bf16x2.f32 %0, %1, %2;" : "=r"(mp) : "f"(y - hy), "f"(x - hx));
}

__device__ __forceinline__ void mma_bf16(float* c, const unsigned* a, const unsigned* b) {
    asm volatile("mma.sync.aligned.m16n8k16.row.col.f32.bf16.bf16.f32 "
        "{%0,%1,%2,%3}, {%4,%5,%6,%7}, {%8,%9}, {%0,%1,%2,%3};"
        : "+f"(c[0]), "+f"(c[1]), "+f"(c[2]), "+f"(c[3])
        : "r"(a[0]), "r"(a[1]), "r"(a[2]), "r"(a[3]), "r"(b[0]), "r"(b[1]));
}

__global__ __launch_bounds__(256, 2) void gemm_mma_kernel(
    const int* __restrict__ doc,
    const float* __restrict__ emb,
    const float* __restrict__ diags,
    const float* __restrict__ bias)
{
    extern __shared__ unsigned sm[];
    unsigned* Abuf[2] = { sm,              sm + 2 * BUFU32 };
    unsigned* Bbuf[2] = { sm + BUFU32,     sm + 3 * BUFU32 };
    __shared__ int docS[128];

    const int tid = threadIdx.x;
    const int wid = tid >> 5;
    const int lane = tid & 31;
    const int wm = wid >> 2;          // 0..1 : m half
    const int wn = wid & 3;           // 0..3 : n quarter
    const int grp = lane >> 2;        // 0..7
    const int tig = lane & 3;         // 0..3
    const int n0 = blockIdx.x * 128;
    const int m0 = blockIdx.y * 128;

    if (tid < 128) docS[tid] = doc[m0 + tid];
    __syncthreads();

    float acc[4][4][4];
#pragma unroll
    for (int i = 0; i < 4; i++)
#pragma unroll
        for (int j = 0; j < 4; j++)
#pragma unroll
            for (int r = 0; r < 4; r++) acc[i][j][r] = 0.0f;

    const float4 fz = make_float4(0.f, 0.f, 0.f, 0.f);
    float4 ra[2], rb[2];

    // ---- prologue: stage 0 load ----
#pragma unroll
    for (int i = 0; i < 2; i++) {
        int slot = tid + i * 256;
        int row = slot >> 2;
        int k4 = (slot & 3) * 4;
        bool kok = k4 < 300;
        ra[i] = kok ? *(const float4*)(emb + (size_t)docS[row] * 300 + k4) : fz;
        int gn = n0 + row;
        rb[i] = (kok && gn < D_COLS) ? *(const float4*)(diags + (size_t)gn * 300 + k4) : fz;
    }
    // convert + store stage 0
#pragma unroll
    for (int i = 0; i < 2; i++) {
        int slot = tid + i * 256;
        int row = slot >> 2;
        int k4 = (slot & 3) * 4;
        unsigned h01, m01, h23, m23;
        bsplit2(ra[i].x, ra[i].y, h01, m01);
        bsplit2(ra[i].z, ra[i].w, h23, m23);
        *(uint4*)(Abuf[0] + row * RSTRIDE + k4) = make_uint4(h01, m01, h23, m23);
        bsplit2(rb[i].x, rb[i].y, h01, m01);
        bsplit2(rb[i].z, rb[i].w, h23, m23);
        *(uint4*)(Bbuf[0] + row * RSTRIDE + k4) = make_uint4(h01, m01, h23, m23);
    }
    __syncthreads();

    for (int c = 0; c < NKS; c++) {
        // prefetch next stage into registers
        if (c + 1 < NKS) {
            const int k0 = (c + 1) * 16;
#pragma unroll
            for (int i = 0; i < 2; i++) {
                int slot = tid + i * 256;
                int row = slot >> 2;
                int k4 = (slot & 3) * 4;
                bool kok = (k0 + k4) < 300;
                ra[i] = kok ? *(const float4*)(emb + (size_t)docS[row] * 300 + k0 + k4) : fz;
                int gn = n0 + row;
                rb[i] = (kok && gn < D_COLS) ? *(const float4*)(diags + (size_t)gn * 300 + k0 + k4) : fz;
            }
        }
        // ---- compute: pure LDS.64 + HMMA, term-major over mt-pairs ----
        {
            const unsigned* As = Abuf[c & 1];
            const unsigned* Bs = Bbuf[c & 1];
            unsigned bh[4][2], bm[4][2];
#pragma unroll
            for (int nt = 0; nt < 4; nt++) {
                const unsigned* p = Bs + (wn * 32 + nt * 8 + grp) * RSTRIDE + tig * 2;
                uint2 v0 = *(const uint2*)p;         // k-pair tig
                uint2 v1 = *(const uint2*)(p + 8);   // k-pair tig+4
                bh[nt][0] = v0.x; bm[nt][0] = v0.y;
                bh[nt][1] = v1.x; bm[nt][1] = v1.y;
            }
#pragma unroll
            for (int mp = 0; mp < 2; mp++) {         // mt pairs {0,1},{2,3}
                const int mt0 = mp * 2, mt1 = mp * 2 + 1;
                const unsigned* p0 = As + (wm * 64 + mt0 * 16 + grp) * RSTRIDE + tig * 2;
                const unsigned* p1 = As + (wm * 64 + mt1 * 16 + grp) * RSTRIDE + tig * 2;
                uint2 a00 = *(const uint2*)p0;
                uint2 a01 = *(const uint2*)(p0 + 8 * RSTRIDE);
                uint2 a02 = *(const uint2*)(p0 + 8);
                uint2 a03 = *(const uint2*)(p0 + 8 * RSTRIDE + 8);
                uint2 a10 = *(const uint2*)p1;
                uint2 a11 = *(const uint2*)(p1 + 8 * RSTRIDE);
                uint2 a12 = *(const uint2*)(p1 + 8);
                uint2 a13 = *(const uint2*)(p1 + 8 * RSTRIDE + 8);
                unsigned ah0[4] = { a00.x, a01.x, a02.x, a03.x };
                unsigned am0[4] = { a00.y, a01.y, a02.y, a03.y };
                unsigned ah1[4] = { a10.x, a11.x, a12.x, a13.x };
                unsigned am1[4] = { a10.y, a11.y, a12.y, a13.y };
                // term hh
#pragma unroll
                for (int nt = 0; nt < 4; nt++) mma_bf16(acc[mt0][nt], ah0, bh[nt]);
#pragma unroll
                for (int nt = 0; nt < 4; nt++) mma_bf16(acc[mt1][nt], ah1, bh[nt]);
                // term mh
#pragma unroll
                for (int nt = 0; nt < 4; nt++) mma_bf16(acc[mt0][nt], am0, bh[nt]);
#pragma unroll
                for (int nt = 0; nt < 4; nt++) mma_bf16(acc[mt1][nt], am1, bh[nt]);
                // term hm
#pragma unroll
                for (int nt = 0; nt < 4; nt++) mma_bf16(acc[mt0][nt], ah0, bm[nt]);
#pragma unroll
                for (int nt = 0; nt < 4; nt++) mma_bf16(acc[mt1][nt], ah1, bm[nt]);
            }
        }
        // ---- convert + store prefetched stage ----
        if (c + 1 < NKS) {
#pragma unroll
            for (int i = 0; i < 2; i++) {
                int slot = tid + i * 256;
                int row = slot >> 2;
                int k4 = (slot & 3) * 4;
                unsigned h01, m01, h23, m23;
                bsplit2(ra[i].x, ra[i].y, h01, m01);
                bsplit2(ra[i].z, ra[i].w, h23, m23);
                *(uint4*)(Abuf[(c + 1) & 1] + row * RSTRIDE + k4) = make_uint4(h01, m01, h23, m23);
                bsplit2(rb[i].x, rb[i].y, h01, m01);
                bsplit2(rb[i].z, rb[i].w, h23, m23);
                *(uint4*)(Bbuf[(c + 1) & 1] + row * RSTRIDE + k4) = make_uint4(h01, m01, h23, m23);
            }
        }
        __syncthreads();
    }

    // ---- epilogue: two 64-row halves via smem, coalesced stores ----
    float* smep = (float*)sm;   // 64 x 132 floats = 33792 B (buffers dead)
    for (int p = 0; p < 2; p++) {
        if (wm == p) {
#pragma unroll
            for (int mt = 0; mt < 4; mt++) {
                const int r0 = mt * 16 + grp;
#pragma unroll
                for (int nt = 0; nt < 4; nt++) {
                    const int cb = wn * 32 + nt * 8 + 2 * tig;
                    smep[r0 * 132 + cb]           = acc[mt][nt][0];
                    smep[r0 * 132 + cb + 1]       = acc[mt][nt][1];
                    smep[(r0 + 8) * 132 + cb]     = acc[mt][nt][2];
                    smep[(r0 + 8) * 132 + cb + 1] = acc[mt][nt][3];
                }
            }
        }
        __syncthreads();
#pragma unroll
        for (int i = 0; i < 8; i++) {
            int slot = tid + i * 256;         // 2048 float4 slots
            int r = slot >> 5;
            int c4 = (slot & 31) * 4;
            int gn = n0 + c4;
            if (gn < D_COLS) {                // 2700 % 4 == 0 -> whole-float4 validity
                float4 bv = *(const float4*)(bias + gn);
                float4 o;
                o.x = 1.0f / (1.0f + __expf(-(smep[r * 132 + c4]     + bv.x)));
                o.y = 1.0f / (1.0f + __expf(-(smep[r * 132 + c4 + 1] + bv.y)));
                o.z = 1.0f / (1.0f + __expf(-(smep[r * 132 + c4 + 2] + bv.z)));
                o.w = 1.0f / (1.0f + __expf(-(smep[r * 132 + c4 + 3] + bv.w)));
                *(float4*)(g_tm + (size_t)(m0 + p * 64 + r) * D_COLS + gn) = o;
            }
        }
        __syncthreads();
    }
}

// =======================================================================
// Kernel 2: chunked parallel scan (unchanged)
// =======================================================================
template <int P>
__device__ __forceinline__ void scan_impl(
    const float* __restrict__ eps_raw,
    float eps_sc, float sls,
    int groupStart, int scoreOff, int chunk)
{
    const int n = threadIdx.x;
    if (n >= 50) return;

    float eps[P - 1];
#pragma unroll
    for (int j = 0; j < P - 1; j++)
        eps[j] = eps_sc * sigmoidf(eps_raw[n * (P - 1) + j]);

    const float* base = g_tm + groupStart + n * 2 * P;

    const int acc_start = chunk * CH;
    int t_begin = acc_start - WARM;
    if (t_begin < 0) t_begin = 0;
    const int t_end = acc_start + CH;
    const int nsteps = t_end - t_begin;

    constexpr int DEPTH = 8;
    float2 buf[DEPTH][P];

#pragma unroll
    for (int d = 0; d < DEPTH; d++) {
        const float2* rp = (const float2*)(base + (size_t)(t_begin + d) * D_COLS);
#pragma unroll
        for (int j = 0; j < P; j++) buf[d][j] = rp[j];
    }

    float h[P];
    h[0] = 1.0f;
#pragma unroll
    for (int i = 1; i < P; i++) h[i] = 0.0f;
    float sc = 0.0f;

    for (int sb2 = 0; sb2 < nsteps; sb2 += DEPTH) {
#pragma unroll
        for (int d = 0; d < DEPTH; d++) {
            const int t = t_begin + sb2 + d;
            float v[2 * P];
#pragma unroll
            for (int j = 0; j < P; j++) {
                v[2 * j]     = buf[d][j].x;
                v[2 * j + 1] = buf[d][j].y;
            }
            const int tn = t + DEPTH;
            if (tn < t_end) {
                const float2* rp = (const float2*)(base + (size_t)tn * D_COLS);
#pragma unroll
                for (int j = 0; j < P; j++) buf[d][j] = rp[j];
            }
#pragma unroll
            for (int i = P - 1; i >= 1; --i)
                h[i] = fmaf(h[i - 1], eps[i - 1], h[i]);
            float res[P];
            res[0] = fmaf(sls * h[0], v[0], 1.0f);
#pragma unroll
            for (int i = 1; i < P; i++)
                res[i] = fmaf(h[i - 1], v[P + i - 1], sls * h[i] * v[i]);
            if (t >= acc_start) sc += res[P - 1];
#pragma unroll
            for (int i = 0; i < P; i++) h[i] = res[i];
        }
    }
    g_part[(scoreOff + n) * NCHUNK + chunk] = sc;
}

__global__ __launch_bounds__(64) void scan_all_kernel(
    const float* e2, const float* e3, const float* e4,
    const float* e5, const float* e6, const float* e7,
    const float* __restrict__ eps_scale,
    const float* __restrict__ sls_scale)
{
    const float eps_sc = sigmoidf(eps_scale[0]);
    const float sls = sigmoidf(sls_scale[0]);
    const int chunk = blockIdx.y;
    switch (blockIdx.x) {
        case 0: scan_impl<2>(e2, eps_sc, sls,    0,   0, chunk); break;
        case 1: scan_impl<3>(e3, eps_sc, sls,  200,  50, chunk); break;
        case 2: scan_impl<4>(e4, eps_sc, sls,  500, 100, chunk); break;
        case 3: scan_impl<5>(e5, eps_sc, sls,  900, 150, chunk); break;
        case 4: scan_impl<6>(e6, eps_sc, sls, 1400, 200, chunk); break;
        case 5: scan_impl<7>(e7, eps_sc, sls, 2000, 250, chunk); break;
    }
}

// ---------------- Kernel 3: partial reduction + tiny MLP head ----------------
__global__ __launch_bounds__(128) void mlp_kernel(
    const float* __restrict__ w1, const float* __restrict__ b1,
    const float* __restrict__ w2, const float* __restrict__ b2,
    float* __restrict__ out)
{
    __shared__ float ssc[300];
    __shared__ float hsh[128];
    const int k = threadIdx.x;

    for (int j = k; j < 300; j += 128) {
        float a = 0.0f;
#pragma unroll
        for (int c = 0; c < NCHUNK; c++) a += g_part[j * NCHUNK + c];
        ssc[j] = a;
    }
    __syncthreads();

    float acc = 0.0f;
    if (k < 100) {
        acc = b1[k];
        for (int j = 0; j < 300; j++)
            acc = fmaf(ssc[j], w1[j * 100 + k], acc);
        acc = fmaxf(acc, 0.0f);
    }
    hsh[k] = (k < 100) ? acc : 0.0f;
    __syncthreads();
    if (k < 2) {
        float o = b2[k];
        for (int i = 0; i < 100; i++)
            o = fmaf(hsh[i], w2[i * 2 + k], o);
        out[k] = o;
    }
}

// ---------------- Launch ----------------
extern "C" void kernel_launch(void* const* d_in, const int* in_sizes, int n_in,
                              void* d_out, int out_size)
{
    const int*   doc       = (const int*)  d_in[0];
    const float* emb       = (const float*)d_in[1];
    const float* diags     = (const float*)d_in[2];
    const float* bias      = (const float*)d_in[3];
    const float* e2        = (const float*)d_in[4];
    const float* e3        = (const float*)d_in[5];
    const float* e4        = (const float*)d_in[6];
    const float* e5        = (const float*)d_in[7];
    const float* e6        = (const float*)d_in[8];
    const float* e7        = (const float*)d_in[9];
    const float* eps_scale = (const float*)d_in[10];
    const float* sls_scale = (const float*)d_in[11];
    const float* w1        = (const float*)d_in[12];
    const float* b1        = (const float*)d_in[13];
    const float* w2        = (const float*)d_in[14];
    const float* b2        = (const float*)d_in[15];
    float* out = (float*)d_out;

    // Opt-in for >48KB-default shared memory (host-side attribute, capture-legal).
    static int smem_set = 0;
    if (!smem_set) {
        cudaFuncSetAttribute(gemm_mma_kernel,
                             cudaFuncAttributeMaxDynamicSharedMemorySize, SMEM_BYTES);
        smem_set = 1;
    }

    gemm_mma_kernel<<<dim3(22, 16), 256, SMEM_BYTES>>>(doc, emb, diags, bias);
    scan_all_kernel<<<dim3(6, NCHUNK), 64>>>(e2, e3, e4, e5, e6, e7, eps_scale, sls_scale);
    mlp_kernel<<<1, 128>>>(w1, b1, w2, b2, out);
}

// round 10
// speedup vs baseline: 1.2184x; 1.2184x over previous
#include <cuda_runtime.h>
#include <math.h>

// ---------------- Scratch (no runtime allocation allowed) ----------------
#define T_LEN 2048
#define D_COLS 2700
#define CH 128
#define WARM 128
#define NCHUNK (T_LEN / CH)         // 16
__device__ __align__(16) float g_tm[T_LEN * D_COLS];
__device__ float g_part[300 * NCHUNK];

__device__ __forceinline__ float sigmoidf(float x) {
    return 1.0f / (1.0f + expf(-x));
}

// =======================================================================
// Kernel 1: gathered GEMM via mma.sync bf16 3-term split + bias + sigmoid
//   C[m][n] = sigmoid( sum_k emb[doc[m]][k] * diags[n][k] + bias[n] )
//   M=2048, N=2700, K=300 (pad 304). CTA 128x128, BK=16, 19 stages.
//   8 warps (2m x 4n), warp tile 64x32 = 4x4 m16n8k16 fragments.
//   Producer splits f32 -> (bf16 hi, bf16 mid) ONCE into smem; consumer is
//   pure LDS.64 + HMMA. Terms: ah*bh + am*bh + ah*bm.
//   MMA schedule: per-mt term-major (hh x4nt, mh x4nt, hm x4nt) ->
//   same-acc reuse distance 4 with round-8 register footprint (no spills).
// =======================================================================
#define NKS 19
#define RSTRIDE 24                  // smem row stride in u32 (96B): LDS.64 conflict-free
#define BUFU32 (128 * RSTRIDE)      // 3072 u32 = 12288 B per operand buffer
#define SMEM_BYTES (4 * BUFU32 * 4) // 49152 (Ah0,Bh0,Ah1,Bh1) -- needs opt-in

// split x,y (k-even, k-odd) into packed bf16 hi-pair and mid-pair
__device__ __forceinline__ void bsplit2(float x, float y, unsigned& hp, unsigned& mp) {
    asm("cvt.rn.bf16x2.f32 %0, %1, %2;" : "=r"(hp) : "f"(y), "f"(x));
    float hx = __uint_as_float(hp << 16);
    float hy = __uint_as_float(hp & 0xFFFF0000u);
    asm("cvt.rn.bf16x2.f32 %0, %1, %2;" : "=r"(mp) : "f"(y - hy), "f"(x - hx));
}

__device__ __forceinline__ void mma_bf16(float* c, const unsigned* a, const unsigned* b) {
    asm volatile("mma.sync.aligned.m16n8k16.row.col.f32.bf16.bf16.f32 "
        "{%0,%1,%2,%3}, {%4,%5,%6,%7}, {%8,%9}, {%0,%1,%2,%3};"
        : "+f"(c[0]), "+f"(c[1]), "+f"(c[2]), "+f"(c[3])
        : "r"(a[0]), "r"(a[1]), "r"(a[2]), "r"(a[3]), "r"(b[0]), "r"(b[1]));
}

__global__ __launch_bounds__(256, 2) void gemm_mma_kernel(
    const int* __restrict__ doc,
    const float* __restrict__ emb,
    const float* __restrict__ diags,
    const float* __restrict__ bias)
{
    extern __shared__ unsigned sm[];
    unsigned* Abuf[2] = { sm,              sm + 2 * BUFU32 };
    unsigned* Bbuf[2] = { sm + BUFU32,     sm + 3 * BUFU32 };
    __shared__ int docS[128];

    const int tid = threadIdx.x;
    const int wid = tid >> 5;
    const int lane = tid & 31;
    const int wm = wid >> 4 >> 0 ? 0 : (wid >> 2); // placeholder avoided below
    const int wmh = wid >> 2;         // 0..1 : m half
    const int wn = wid & 3;           // 0..3 : n quarter
    const int grp = lane >> 2;        // 0..7
    const int tig = lane & 3;         // 0..3
    const int n0 = blockIdx.x * 128;
    const int m0 = blockIdx.y * 128;
    (void)wm;

    if (tid < 128) docS[tid] = doc[m0 + tid];
    __syncthreads();

    float acc[4][4][4];
#pragma unroll
    for (int i = 0; i < 4; i++)
#pragma unroll
        for (int j = 0; j < 4; j++)
#pragma unroll
            for (int r = 0; r < 4; r++) acc[i][j][r] = 0.0f;

    const float4 fz = make_float4(0.f, 0.f, 0.f, 0.f);
    float4 ra[2], rb[2];

    // ---- per-thread hoisted gmem pointers (advance += 16 per stage) ----
    const int row0 = tid >> 2;               // slot i=0
    const int row1 = (tid + 256) >> 2;       // slot i=1 (= row0 + 64)
    const int k4t = (tid & 3) * 4;           // same for both slots
    const float* pA0 = emb + (size_t)docS[row0] * 300 + k4t;
    const float* pA1 = emb + (size_t)docS[row1] * 300 + k4t;
    const bool gok0 = (n0 + row0) < D_COLS;
    const bool gok1 = (n0 + row1) < D_COLS;
    const float* pB0 = diags + (size_t)(n0 + row0) * 300 + k4t;
    const float* pB1 = diags + (size_t)(n0 + row1) * 300 + k4t;

    // ---- prologue: stage 0 load + convert + store ----
    {
        bool kok = k4t < 300;
        ra[0] = kok ? *(const float4*)pA0 : fz;
        ra[1] = kok ? *(const float4*)pA1 : fz;
        rb[0] = (kok && gok0) ? *(const float4*)pB0 : fz;
        rb[1] = (kok && gok1) ? *(const float4*)pB1 : fz;
        pA0 += 16; pA1 += 16; pB0 += 16; pB1 += 16;
    }
#pragma unroll
    for (int i = 0; i < 2; i++) {
        int row = i ? row1 : row0;
        unsigned h01, m01, h23, m23;
        bsplit2(ra[i].x, ra[i].y, h01, m01);
        bsplit2(ra[i].z, ra[i].w, h23, m23);
        *(uint4*)(Abuf[0] + row * RSTRIDE + k4t) = make_uint4(h01, m01, h23, m23);
        bsplit2(rb[i].x, rb[i].y, h01, m01);
        bsplit2(rb[i].z, rb[i].w, h23, m23);
        *(uint4*)(Bbuf[0] + row * RSTRIDE + k4t) = make_uint4(h01, m01, h23, m23);
    }
    __syncthreads();

    for (int c = 0; c < NKS; c++) {
        // prefetch next stage into registers (hoisted pointers)
        if (c + 1 < NKS) {
            const bool kok = ((c + 1) * 16 + k4t) < 300;
            ra[0] = kok ? *(const float4*)pA0 : fz;
            ra[1] = kok ? *(const float4*)pA1 : fz;
            rb[0] = (kok && gok0) ? *(const float4*)pB0 : fz;
            rb[1] = (kok && gok1) ? *(const float4*)pB1 : fz;
            pA0 += 16; pA1 += 16; pB0 += 16; pB1 += 16;
        }
        // ---- compute: pure LDS.64 + HMMA, per-mt term-major ----
        {
            const unsigned* As = Abuf[c & 1];
            const unsigned* Bs = Bbuf[c & 1];
            unsigned bh[4][2], bm[4][2];
#pragma unroll
            for (int nt = 0; nt < 4; nt++) {
                const unsigned* p = Bs + (wn * 32 + nt * 8 + grp) * RSTRIDE + tig * 2;
                uint2 v0 = *(const uint2*)p;         // k-pair tig
                uint2 v1 = *(const uint2*)(p + 8);   // k-pair tig+4
                bh[nt][0] = v0.x; bm[nt][0] = v0.y;
                bh[nt][1] = v1.x; bm[nt][1] = v1.y;
            }
#pragma unroll
            for (int mt = 0; mt < 4; mt++) {
                const unsigned* p = As + (wmh * 64 + mt * 16 + grp) * RSTRIDE + tig * 2;
                uint2 a0 = *(const uint2*)p;
                uint2 a1 = *(const uint2*)(p + 8 * RSTRIDE);
                uint2 a2 = *(const uint2*)(p + 8);
                uint2 a3 = *(const uint2*)(p + 8 * RSTRIDE + 8);
                unsigned ah[4] = { a0.x, a1.x, a2.x, a3.x };
                unsigned am[4] = { a0.y, a1.y, a2.y, a3.y };
                // term-major: same-acc reuse distance = 4 MMAs
#pragma unroll
                for (int nt = 0; nt < 4; nt++) mma_bf16(acc[mt][nt], ah, bh[nt]);
#pragma unroll
                for (int nt = 0; nt < 4; nt++) mma_bf16(acc[mt][nt], am, bh[nt]);
#pragma unroll
                for (int nt = 0; nt < 4; nt++) mma_bf16(acc[mt][nt], ah, bm[nt]);
            }
        }
        // ---- convert + store prefetched stage ----
        if (c + 1 < NKS) {
#pragma unroll
            for (int i = 0; i < 2; i++) {
                int row = i ? row1 : row0;
                unsigned h01, m01, h23, m23;
                bsplit2(ra[i].x, ra[i].y, h01, m01);
                bsplit2(ra[i].z, ra[i].w, h23, m23);
                *(uint4*)(Abuf[(c + 1) & 1] + row * RSTRIDE + k4t) = make_uint4(h01, m01, h23, m23);
                bsplit2(rb[i].x, rb[i].y, h01, m01);
                bsplit2(rb[i].z, rb[i].w, h23, m23);
                *(uint4*)(Bbuf[(c + 1) & 1] + row * RSTRIDE + k4t) = make_uint4(h01, m01, h23, m23);
            }
        }
        __syncthreads();
    }

    // ---- epilogue: two 64-row halves via smem, coalesced stores ----
    float* smep = (float*)sm;   // 64 x 132 floats = 33792 B (buffers dead)
    for (int p = 0; p < 2; p++) {
        if (wmh == p) {
#pragma unroll
            for (int mt = 0; mt < 4; mt++) {
                const int r0 = mt * 16 + grp;
#pragma unroll
                for (int nt = 0; nt < 4; nt++) {
                    const int cb = wn * 32 + nt * 8 + 2 * tig;
                    smep[r0 * 132 + cb]           = acc[mt][nt][0];
                    smep[r0 * 132 + cb + 1]       = acc[mt][nt][1];
                    smep[(r0 + 8) * 132 + cb]     = acc[mt][nt][2];
                    smep[(r0 + 8) * 132 + cb + 1] = acc[mt][nt][3];
                }
            }
        }
        __syncthreads();
#pragma unroll
        for (int i = 0; i < 8; i++) {
            int slot = tid + i * 256;         // 2048 float4 slots
            int r = slot >> 5;
            int c4 = (slot & 31) * 4;
            int gn = n0 + c4;
            if (gn < D_COLS) {                // 2700 % 4 == 0 -> whole-float4 validity
                float4 bv = *(const float4*)(bias + gn);
                float4 o;
                o.x = 1.0f / (1.0f + __expf(-(smep[r * 132 + c4]     + bv.x)));
                o.y = 1.0f / (1.0f + __expf(-(smep[r * 132 + c4 + 1] + bv.y)));
                o.z = 1.0f / (1.0f + __expf(-(smep[r * 132 + c4 + 2] + bv.z)));
                o.w = 1.0f / (1.0f + __expf(-(smep[r * 132 + c4 + 3] + bv.w)));
                *(float4*)(g_tm + (size_t)(m0 + p * 64 + r) * D_COLS + gn) = o;
            }
        }
        __syncthreads();
    }
}

// =======================================================================
// Kernel 2: chunked parallel scan (unchanged)
// =======================================================================
template <int P>
__device__ __forceinline__ void scan_impl(
    const float* __restrict__ eps_raw,
    float eps_sc, float sls,
    int groupStart, int scoreOff, int chunk)
{
    const int n = threadIdx.x;
    if (n >= 50) return;

    float eps[P - 1];
#pragma unroll
    for (int j = 0; j < P - 1; j++)
        eps[j] = eps_sc * sigmoidf(eps_raw[n * (P - 1) + j]);

    const float* base = g_tm + groupStart + n * 2 * P;

    const int acc_start = chunk * CH;
    int t_begin = acc_start - WARM;
    if (t_begin < 0) t_begin = 0;
    const int t_end = acc_start + CH;
    const int nsteps = t_end - t_begin;

    constexpr int DEPTH = 8;
    float2 buf[DEPTH][P];

#pragma unroll
    for (int d = 0; d < DEPTH; d++) {
        const float2* rp = (const float2*)(base + (size_t)(t_begin + d) * D_COLS);
#pragma unroll
        for (int j = 0; j < P; j++) buf[d][j] = rp[j];
    }

    float h[P];
    h[0] = 1.0f;
#pragma unroll
    for (int i = 1; i < P; i++) h[i] = 0.0f;
    float sc = 0.0f;

    for (int sb2 = 0; sb2 < nsteps; sb2 += DEPTH) {
#pragma unroll
        for (int d = 0; d < DEPTH; d++) {
            const int t = t_begin + sb2 + d;
            float v[2 * P];
#pragma unroll
            for (int j = 0; j < P; j++) {
                v[2 * j]     = buf[d][j].x;
                v[2 * j + 1] = buf[d][j].y;
            }
            const int tn = t + DEPTH;
            if (tn < t_end) {
                const float2* rp = (const float2*)(base + (size_t)tn * D_COLS);
#pragma unroll
                for (int j = 0; j < P; j++) buf[d][j] = rp[j];
            }
#pragma unroll
            for (int i = P - 1; i >= 1; --i)
                h[i] = fmaf(h[i - 1], eps[i - 1], h[i]);
            float res[P];
            res[0] = fmaf(sls * h[0], v[0], 1.0f);
#pragma unroll
            for (int i = 1; i < P; i++)
                res[i] = fmaf(h[i - 1], v[P + i - 1], sls * h[i] * v[i]);
            if (t >= acc_start) sc += res[P - 1];
#pragma unroll
            for (int i = 0; i < P; i++) h[i] = res[i];
        }
    }
    g_part[(scoreOff + n) * NCHUNK + chunk] = sc;
}

__global__ __launch_bounds__(64) void scan_all_kernel(
    const float* e2, const float* e3, const float* e4,
    const float* e5, const float* e6, const float* e7,
    const float* __restrict__ eps_scale,
    const float* __restrict__ sls_scale)
{
    const float eps_sc = sigmoidf(eps_scale[0]);
    const float sls = sigmoidf(sls_scale[0]);
    const int chunk = blockIdx.y;
    switch (blockIdx.x) {
        case 0: scan_impl<2>(e2, eps_sc, sls,    0,   0, chunk); break;
        case 1: scan_impl<3>(e3, eps_sc, sls,  200,  50, chunk); break;
        case 2: scan_impl<4>(e4, eps_sc, sls,  500, 100, chunk); break;
        case 3: scan_impl<5>(e5, eps_sc, sls,  900, 150, chunk); break;
        case 4: scan_impl<6>(e6, eps_sc, sls, 1400, 200, chunk); break;
        case 5: scan_impl<7>(e7, eps_sc, sls, 2000, 250, chunk); break;
    }
}

// ---------------- Kernel 3: partial reduction + tiny MLP head ----------------
__global__ __launch_bounds__(128) void mlp_kernel(
    const float* __restrict__ w1, const float* __restrict__ b1,
    const float* __restrict__ w2, const float* __restrict__ b2,
    float* __restrict__ out)
{
    __shared__ float ssc[300];
    __shared__ float hsh[128];
    const int k = threadIdx.x;

    for (int j = k; j < 300; j += 128) {
        float a = 0.0f;
#pragma unroll
        for (int c = 0; c < NCHUNK; c++) a += g_part[j * NCHUNK + c];
        ssc[j] = a;
    }
    __syncthreads();

    float acc = 0.0f;
    if (k < 100) {
        acc = b1[k];
        for (int j = 0; j < 300; j++)
            acc = fmaf(ssc[j], w1[j * 100 + k], acc);
        acc = fmaxf(acc, 0.0f);
    }
    hsh[k] = (k < 100) ? acc : 0.0f;
    __syncthreads();
    if (k < 2) {
        float o = b2[k];
        for (int i = 0; i < 100; i++)
            o = fmaf(hsh[i], w2[i * 2 + k], o);
        out[k] = o;
    }
}

// ---------------- Launch ----------------
extern "C" void kernel_launch(void* const* d_in, const int* in_sizes, int n_in,
                              void* d_out, int out_size)
{
    const int*   doc       = (const int*)  d_in[0];
    const float* emb       = (const float*)d_in[1];
    const float* diags     = (const float*)d_in[2];
    const float* bias      = (const float*)d_in[3];
    const float* e2        = (const float*)d_in[4];
    const float* e3        = (const float*)d_in[5];
    const float* e4        = (const float*)d_in[6];
    const float* e5        = (const float*)d_in[7];
    const float* e6        = (const float*)d_in[8];
    const float* e7        = (const float*)d_in[9];
    const float* eps_scale = (const float*)d_in[10];
    const float* sls_scale = (const float*)d_in[11];
    const float* w1        = (const float*)d_in[12];
    const float* b1        = (const float*)d_in[13];
    const float* w2        = (const float*)d_in[14];
    const float* b2        = (const float*)d_in[15];
    float* out = (float*)d_out;

    // Opt-in for >48KB-default shared memory (host-side attribute, capture-legal).
    static int smem_set = 0;
    if (!smem_set) {
        cudaFuncSetAttribute(gemm_mma_kernel,
                             cudaFuncAttributeMaxDynamicSharedMemorySize, SMEM_BYTES);
        smem_set = 1;
    }

    gemm_mma_kernel<<<dim3(22, 16), 256, SMEM_BYTES>>>(doc, emb, diags, bias);
    scan_all_kernel<<<dim3(6, NCHUNK), 64>>>(e2, e3, e4, e5, e6, e7, eps_scale, sls_scale);
    mlp_kernel<<<1, 128>>>(w1, b1, w2, b2, out);
}

// round 11
// speedup vs baseline: 1.2416x; 1.0191x over previous
#include <cuda_runtime.h>
#include <math.h>

// ---------------- Scratch (no runtime allocation allowed) ----------------
#define T_LEN 2048
#define D_COLS 2700
#define CH 128
#define WARM 128
#define NCHUNK (T_LEN / CH)         // 16
__device__ __align__(16) float g_tm[T_LEN * D_COLS];
__device__ float g_part[300 * NCHUNK];

__device__ __forceinline__ float sigmoidf(float x) {
    return 1.0f / (1.0f + expf(-x));
}

// =======================================================================
// Kernel 1: gathered GEMM via mma.sync bf16 3-term split + bias + sigmoid
//   C[m][n] = sigmoid( sum_k emb[doc[m]][k] * diags[n][k] + bias[n] )
//   M=2048, N=2700, K=300 (pad 304). CTA 128x96, BK=16, 19 stages.
//   8 warps (2m x 4n), warp tile 64x24 = 4x3 m16n8k16 fragments.
//   Acc = 48 regs (vs 64 @BN=128) -> fits the 128-reg/2-CTA cap, no spills.
//   Producer splits f32 -> (bf16 hi, bf16 mid) ONCE into smem; consumer is
//   pure LDS.64 + HMMA. Terms per acc (round-8 order): hh, mh, hm.
// =======================================================================
#define NKS 19
#define NTW 3                        // n-fragments per warp (24 cols)
#define BN 96
#define RSTRIDE 24                   // smem row stride in u32 (96B): LDS.64 conflict-free
#define ABUFU32 (128 * RSTRIDE)      // 3072 u32
#define BBUFU32 (96 * RSTRIDE)       // 2304 u32
#define STAGEU32 (ABUFU32 + BBUFU32) // 5376 u32
#define SMEM_BYTES (2 * STAGEU32 * 4) // 43008 B (< 48K default)

// split x,y (k-even, k-odd) into packed bf16 hi-pair and mid-pair
__device__ __forceinline__ void bsplit2(float x, float y, unsigned& hp, unsigned& mp) {
    asm("cvt.rn.bf16x2.f32 %0, %1, %2;" : "=r"(hp) : "f"(y), "f"(x));
    float hx = __uint_as_float(hp << 16);
    float hy = __uint_as_float(hp & 0xFFFF0000u);
    asm("cvt.rn.bf16x2.f32 %0, %1, %2;" : "=r"(mp) : "f"(y - hy), "f"(x - hx));
}

__device__ __forceinline__ void mma_bf16(float* c, const unsigned* a, const unsigned* b) {
    asm volatile("mma.sync.aligned.m16n8k16.row.col.f32.bf16.bf16.f32 "
        "{%0,%1,%2,%3}, {%4,%5,%6,%7}, {%8,%9}, {%0,%1,%2,%3};"
        : "+f"(c[0]), "+f"(c[1]), "+f"(c[2]), "+f"(c[3])
        : "r"(a[0]), "r"(a[1]), "r"(a[2]), "r"(a[3]), "r"(b[0]), "r"(b[1]));
}

__global__ __launch_bounds__(256, 2) void gemm_mma_kernel(
    const int* __restrict__ doc,
    const float* __restrict__ emb,
    const float* __restrict__ diags,
    const float* __restrict__ bias)
{
    extern __shared__ unsigned sm[];
    unsigned* Abuf[2] = { sm,               sm + STAGEU32 };
    unsigned* Bbuf[2] = { sm + ABUFU32,     sm + STAGEU32 + ABUFU32 };
    __shared__ int docS[128];

    const int tid = threadIdx.x;
    const int wid = tid >> 5;
    const int lane = tid & 31;
    const int wmh = wid >> 2;         // 0..1 : m half
    const int wn = wid & 3;           // 0..3 : n quarter (24 cols each)
    const int grp = lane >> 2;        // 0..7
    const int tig = lane & 3;         // 0..3
    const int n0 = blockIdx.x * BN;
    const int m0 = blockIdx.y * 128;

    if (tid < 128) docS[tid] = doc[m0 + tid];
    __syncthreads();

    float acc[4][NTW][4];
#pragma unroll
    for (int i = 0; i < 4; i++)
#pragma unroll
        for (int j = 0; j < NTW; j++)
#pragma unroll
            for (int r = 0; r < 4; r++) acc[i][j][r] = 0.0f;

    const float4 fz = make_float4(0.f, 0.f, 0.f, 0.f);
    float4 ra[2], rb[2];

    // ---- per-thread hoisted gmem pointers (advance += 16 per stage) ----
    const int rowA0 = tid >> 2;              // 0..63
    const int rowA1 = 64 + rowA0;            // 64..127
    const int k4t = (tid & 3) * 4;
    const float* pA0 = emb + (size_t)docS[rowA0] * 300 + k4t;
    const float* pA1 = emb + (size_t)docS[rowA1] * 300 + k4t;
    // B: rows 0..95. slot0 = tid -> row tid>>2 (0..63); slot1 only tid<128 -> row 64..95
    const int rowB0 = rowA0;
    const int rowB1 = 64 + rowA0;            // only meaningful for tid<128
    const bool hasB1 = tid < 128;
    const bool gokB0 = (n0 + rowB0) < D_COLS;
    const bool gokB1 = hasB1 && ((n0 + rowB1) < D_COLS);
    const float* pB0 = diags + (size_t)(n0 + rowB0) * 300 + k4t;
    const float* pB1 = diags + (size_t)(n0 + (hasB1 ? rowB1 : rowB0)) * 300 + k4t;

    // ---- prologue: stage 0 load + convert + store ----
    {
        bool kok = k4t < 300;
        ra[0] = kok ? *(const float4*)pA0 : fz;
        ra[1] = kok ? *(const float4*)pA1 : fz;
        rb[0] = (kok && gokB0) ? *(const float4*)pB0 : fz;
        rb[1] = (kok && gokB1) ? *(const float4*)pB1 : fz;
        pA0 += 16; pA1 += 16; pB0 += 16; pB1 += 16;
    }
    {
        unsigned h01, m01, h23, m23;
        bsplit2(ra[0].x, ra[0].y, h01, m01);
        bsplit2(ra[0].z, ra[0].w, h23, m23);
        *(uint4*)(Abuf[0] + rowA0 * RSTRIDE + k4t) = make_uint4(h01, m01, h23, m23);
        bsplit2(ra[1].x, ra[1].y, h01, m01);
        bsplit2(ra[1].z, ra[1].w, h23, m23);
        *(uint4*)(Abuf[0] + rowA1 * RSTRIDE + k4t) = make_uint4(h01, m01, h23, m23);
        bsplit2(rb[0].x, rb[0].y, h01, m01);
        bsplit2(rb[0].z, rb[0].w, h23, m23);
        *(uint4*)(Bbuf[0] + rowB0 * RSTRIDE + k4t) = make_uint4(h01, m01, h23, m23);
        if (hasB1) {
            bsplit2(rb[1].x, rb[1].y, h01, m01);
            bsplit2(rb[1].z, rb[1].w, h23, m23);
            *(uint4*)(Bbuf[0] + rowB1 * RSTRIDE + k4t) = make_uint4(h01, m01, h23, m23);
        }
    }
    __syncthreads();

    for (int c = 0; c < NKS; c++) {
        // prefetch next stage into registers
        if (c + 1 < NKS) {
            const bool kok = ((c + 1) * 16 + k4t) < 300;
            ra[0] = kok ? *(const float4*)pA0 : fz;
            ra[1] = kok ? *(const float4*)pA1 : fz;
            rb[0] = (kok && gokB0) ? *(const float4*)pB0 : fz;
            rb[1] = (kok && gokB1) ? *(const float4*)pB1 : fz;
            pA0 += 16; pA1 += 16; pB0 += 16; pB1 += 16;
        }
        // ---- compute: pure LDS.64 + HMMA (round-8 schedule) ----
        {
            const unsigned* As = Abuf[c & 1];
            const unsigned* Bs = Bbuf[c & 1];
            unsigned bh[NTW][2], bm[NTW][2];
#pragma unroll
            for (int nt = 0; nt < NTW; nt++) {
                const unsigned* p = Bs + (wn * 24 + nt * 8 + grp) * RSTRIDE + tig * 2;
                uint2 v0 = *(const uint2*)p;         // k-pair tig
                uint2 v1 = *(const uint2*)(p + 8);   // k-pair tig+4
                bh[nt][0] = v0.x; bm[nt][0] = v0.y;
                bh[nt][1] = v1.x; bm[nt][1] = v1.y;
            }
#pragma unroll
            for (int mt = 0; mt < 4; mt++) {
                const unsigned* p = As + (wmh * 64 + mt * 16 + grp) * RSTRIDE + tig * 2;
                uint2 a0 = *(const uint2*)p;
                uint2 a1 = *(const uint2*)(p + 8 * RSTRIDE);
                uint2 a2 = *(const uint2*)(p + 8);
                uint2 a3 = *(const uint2*)(p + 8 * RSTRIDE + 8);
                unsigned ah[4] = { a0.x, a1.x, a2.x, a3.x };
                unsigned am[4] = { a0.y, a1.y, a2.y, a3.y };
#pragma unroll
                for (int nt = 0; nt < NTW; nt++) {
                    mma_bf16(acc[mt][nt], ah, bh[nt]);
                    mma_bf16(acc[mt][nt], am, bh[nt]);
                    mma_bf16(acc[mt][nt], ah, bm[nt]);
                }
            }
        }
        // ---- convert + store prefetched stage ----
        if (c + 1 < NKS) {
            unsigned* An = Abuf[(c + 1) & 1];
            unsigned* Bn = Bbuf[(c + 1) & 1];
            unsigned h01, m01, h23, m23;
            bsplit2(ra[0].x, ra[0].y, h01, m01);
            bsplit2(ra[0].z, ra[0].w, h23, m23);
            *(uint4*)(An + rowA0 * RSTRIDE + k4t) = make_uint4(h01, m01, h23, m23);
            bsplit2(ra[1].x, ra[1].y, h01, m01);
            bsplit2(ra[1].z, ra[1].w, h23, m23);
            *(uint4*)(An + rowA1 * RSTRIDE + k4t) = make_uint4(h01, m01, h23, m23);
            bsplit2(rb[0].x, rb[0].y, h01, m01);
            bsplit2(rb[0].z, rb[0].w, h23, m23);
            *(uint4*)(Bn + rowB0 * RSTRIDE + k4t) = make_uint4(h01, m01, h23, m23);
            if (hasB1) {
                bsplit2(rb[1].x, rb[1].y, h01, m01);
                bsplit2(rb[1].z, rb[1].w, h23, m23);
                *(uint4*)(Bn + rowB1 * RSTRIDE + k4t) = make_uint4(h01, m01, h23, m23);
            }
        }
        __syncthreads();
    }

    // ---- epilogue: two 64-row halves via smem (stride 100), coalesced stores ----
    float* smep = (float*)sm;   // 64 x 100 floats = 25600 B (buffers dead)
    for (int p = 0; p < 2; p++) {
        if (wmh == p) {
#pragma unroll
            for (int mt = 0; mt < 4; mt++) {
                const int r0 = mt * 16 + grp;
#pragma unroll
                for (int nt = 0; nt < NTW; nt++) {
                    const int cb = wn * 24 + nt * 8 + 2 * tig;
                    smep[r0 * 100 + cb]           = acc[mt][nt][0];
                    smep[r0 * 100 + cb + 1]       = acc[mt][nt][1];
                    smep[(r0 + 8) * 100 + cb]     = acc[mt][nt][2];
                    smep[(r0 + 8) * 100 + cb + 1] = acc[mt][nt][3];
                }
            }
        }
        __syncthreads();
#pragma unroll
        for (int i = 0; i < 6; i++) {
            int slot = tid + i * 256;         // 1536 float4 slots (64 rows x 24)
            int r = slot / 24;
            int c4 = (slot % 24) * 4;
            int gn = n0 + c4;
            if (gn < D_COLS) {                // 2700 % 4 == 0 -> whole-float4 validity
                float4 bv = *(const float4*)(bias + gn);
                float4 o;
                o.x = 1.0f / (1.0f + __expf(-(smep[r * 100 + c4]     + bv.x)));
                o.y = 1.0f / (1.0f + __expf(-(smep[r * 100 + c4 + 1] + bv.y)));
                o.z = 1.0f / (1.0f + __expf(-(smep[r * 100 + c4 + 2] + bv.z)));
                o.w = 1.0f / (1.0f + __expf(-(smep[r * 100 + c4 + 3] + bv.w)));
                *(float4*)(g_tm + (size_t)(m0 + p * 64 + r) * D_COLS + gn) = o;
            }
        }
        __syncthreads();
    }
}

// =======================================================================
// Kernel 2: chunked parallel scan (unchanged)
// =======================================================================
template <int P>
__device__ __forceinline__ void scan_impl(
    const float* __restrict__ eps_raw,
    float eps_sc, float sls,
    int groupStart, int scoreOff, int chunk)
{
    const int n = threadIdx.x;
    if (n >= 50) return;

    float eps[P - 1];
#pragma unroll
    for (int j = 0; j < P - 1; j++)
        eps[j] = eps_sc * sigmoidf(eps_raw[n * (P - 1) + j]);

    const float* base = g_tm + groupStart + n * 2 * P;

    const int acc_start = chunk * CH;
    int t_begin = acc_start - WARM;
    if (t_begin < 0) t_begin = 0;
    const int t_end = acc_start + CH;
    const int nsteps = t_end - t_begin;

    constexpr int DEPTH = 8;
    float2 buf[DEPTH][P];

#pragma unroll
    for (int d = 0; d < DEPTH; d++) {
        const float2* rp = (const float2*)(base + (size_t)(t_begin + d) * D_COLS);
#pragma unroll
        for (int j = 0; j < P; j++) buf[d][j] = rp[j];
    }

    float h[P];
    h[0] = 1.0f;
#pragma unroll
    for (int i = 1; i < P; i++) h[i] = 0.0f;
    float sc = 0.0f;

    for (int sb2 = 0; sb2 < nsteps; sb2 += DEPTH) {
#pragma unroll
        for (int d = 0; d < DEPTH; d++) {
            const int t = t_begin + sb2 + d;
            float v[2 * P];
#pragma unroll
            for (int j = 0; j < P; j++) {
                v[2 * j]     = buf[d][j].x;
                v[2 * j + 1] = buf[d][j].y;
            }
            const int tn = t + DEPTH;
            if (tn < t_end) {
                const float2* rp = (const float2*)(base + (size_t)tn * D_COLS);
#pragma unroll
                for (int j = 0; j < P; j++) buf[d][j] = rp[j];
            }
#pragma unroll
            for (int i = P - 1; i >= 1; --i)
                h[i] = fmaf(h[i - 1], eps[i - 1], h[i]);
            float res[P];
            res[0] = fmaf(sls * h[0], v[0], 1.0f);
#pragma unroll
            for (int i = 1; i < P; i++)
                res[i] = fmaf(h[i - 1], v[P + i - 1], sls * h[i] * v[i]);
            if (t >= acc_start) sc += res[P - 1];
#pragma unroll
            for (int i = 0; i < P; i++) h[i] = res[i];
        }
    }
    g_part[(scoreOff + n) * NCHUNK + chunk] = sc;
}

__global__ __launch_bounds__(64) void scan_all_kernel(
    const float* e2, const float* e3, const float* e4,
    const float* e5, const float* e6, const float* e7,
    const float* __restrict__ eps_scale,
    const float* __restrict__ sls_scale)
{
    const float eps_sc = sigmoidf(eps_scale[0]);
    const float sls = sigmoidf(sls_scale[0]);
    const int chunk = blockIdx.y;
    switch (blockIdx.x) {
        case 0: scan_impl<2>(e2, eps_sc, sls,    0,   0, chunk); break;
        case 1: scan_impl<3>(e3, eps_sc, sls,  200,  50, chunk); break;
        case 2: scan_impl<4>(e4, eps_sc, sls,  500, 100, chunk); break;
        case 3: scan_impl<5>(e5, eps_sc, sls,  900, 150, chunk); break;
        case 4: scan_impl<6>(e6, eps_sc, sls, 1400, 200, chunk); break;
        case 5: scan_impl<7>(e7, eps_sc, sls, 2000, 250, chunk); break;
    }
}

// ---------------- Kernel 3: partial reduction + tiny MLP head ----------------
__global__ __launch_bounds__(128) void mlp_kernel(
    const float* __restrict__ w1, const float* __restrict__ b1,
    const float* __restrict__ w2, const float* __restrict__ b2,
    float* __restrict__ out)
{
    __shared__ float ssc[300];
    __shared__ float hsh[128];
    const int k = threadIdx.x;

    for (int j = k; j < 300; j += 128) {
        float a = 0.0f;
#pragma unroll
        for (int c = 0; c < NCHUNK; c++) a += g_part[j * NCHUNK + c];
        ssc[j] = a;
    }
    __syncthreads();

    float acc = 0.0f;
    if (k < 100) {
        acc = b1[k];
        for (int j = 0; j < 300; j++)
            acc = fmaf(ssc[j], w1[j * 100 + k], acc);
        acc = fmaxf(acc, 0.0f);
    }
    hsh[k] = (k < 100) ? acc : 0.0f;
    __syncthreads();
    if (k < 2) {
        float o = b2[k];
        for (int i = 0; i < 100; i++)
            o = fmaf(hsh[i], w2[i * 2 + k], o);
        out[k] = o;
    }
}

// ---------------- Launch ----------------
extern "C" void kernel_launch(void* const* d_in, const int* in_sizes, int n_in,
                              void* d_out, int out_size)
{
    const int*   doc       = (const int*)  d_in[0];
    const float* emb       = (const float*)d_in[1];
    const float* diags     = (const float*)d_in[2];
    const float* bias      = (const float*)d_in[3];
    const float* e2        = (const float*)d_in[4];
    const float* e3        = (const float*)d_in[5];
    const float* e4        = (const float*)d_in[6];
    const float* e5        = (const float*)d_in[7];
    const float* e6        = (const float*)d_in[8];
    const float* e7        = (const float*)d_in[9];
    const float* eps_scale = (const float*)d_in[10];
    const float* sls_scale = (const float*)d_in[11];
    const float* w1        = (const float*)d_in[12];
    const float* b1        = (const float*)d_in[13];
    const float* w2        = (const float*)d_in[14];
    const float* b2        = (const float*)d_in[15];
    float* out = (float*)d_out;

    gemm_mma_kernel<<<dim3((D_COLS + BN - 1) / BN, 16), 256, SMEM_BYTES>>>(doc, emb, diags, bias);
    scan_all_kernel<<<dim3(6, NCHUNK), 64>>>(e2, e3, e4, e5, e6, e7, eps_scale, sls_scale);
    mlp_kernel<<<1, 128>>>(w1, b1, w2, b2, out);
}

// round 12
// speedup vs baseline: 1.2446x; 1.0024x over previous
#include <cuda_runtime.h>
#include <math.h>

// ---------------- Scratch (no runtime allocation allowed) ----------------
#define T_LEN 2048
#define D_COLS 2700
#define CH 128
#define WARM 128
#define NCHUNK (T_LEN / CH)         // 16
__device__ __align__(16) float g_tm[T_LEN * D_COLS];
__device__ float g_part[300 * NCHUNK];

__device__ __forceinline__ float sigmoidf(float x) {
    return 1.0f / (1.0f + expf(-x));
}

// =======================================================================
// Kernel 1: gathered GEMM via mma.sync bf16 3-term split + bias + sigmoid
//   C[m][n] = sigmoid( sum_k emb[doc[m]][k] * diags[n][k] + bias[n] )
//   M=2048, N=2700, K=300 (pad 304). CTA 64x96, BK=16, 19 stages.
//   8 warps (2m x 4n), warp tile 32x24 = 2x3 m16n8k16 fragments.
//   3 CTAs/SM (reg cap 85, demand ~82 -> no spills), 24 warps/SM.
//   Producer splits f32 -> (bf16 hi, bf16 mid) ONCE into smem; consumer is
//   pure LDS.64 + HMMA. Terms per acc (round-8 order): hh, mh, hm.
// =======================================================================
#define BM 64
#define BN 96
#define NTW 3                        // n-fragments per warp (24 cols)
#define NKS 19
#define RSTRIDE 24                   // smem row stride in u32 (96B): LDS.64 conflict-free
#define ABUFU32 (BM * RSTRIDE)       // 1536 u32
#define BBUFU32 (BN * RSTRIDE)       // 2304 u32
#define STAGEU32 (ABUFU32 + BBUFU32) // 3840 u32
#define SMEM_BYTES (2 * STAGEU32 * 4) // 30720 B

// split x,y (k-even, k-odd) into packed bf16 hi-pair and mid-pair
__device__ __forceinline__ void bsplit2(float x, float y, unsigned& hp, unsigned& mp) {
    asm("cvt.rn.bf16x2.f32 %0, %1, %2;" : "=r"(hp) : "f"(y), "f"(x));
    float hx = __uint_as_float(hp << 16);
    float hy = __uint_as_float(hp & 0xFFFF0000u);
    asm("cvt.rn.bf16x2.f32 %0, %1, %2;" : "=r"(mp) : "f"(y - hy), "f"(x - hx));
}

__device__ __forceinline__ void mma_bf16(float* c, const unsigned* a, const unsigned* b) {
    asm volatile("mma.sync.aligned.m16n8k16.row.col.f32.bf16.bf16.f32 "
        "{%0,%1,%2,%3}, {%4,%5,%6,%7}, {%8,%9}, {%0,%1,%2,%3};"
        : "+f"(c[0]), "+f"(c[1]), "+f"(c[2]), "+f"(c[3])
        : "r"(a[0]), "r"(a[1]), "r"(a[2]), "r"(a[3]), "r"(b[0]), "r"(b[1]));
}

__global__ __launch_bounds__(256, 3) void gemm_mma_kernel(
    const int* __restrict__ doc,
    const float* __restrict__ emb,
    const float* __restrict__ diags,
    const float* __restrict__ bias)
{
    extern __shared__ unsigned sm[];
    unsigned* Abuf[2] = { sm,               sm + STAGEU32 };
    unsigned* Bbuf[2] = { sm + ABUFU32,     sm + STAGEU32 + ABUFU32 };

    const int tid = threadIdx.x;
    const int wid = tid >> 5;
    const int lane = tid & 31;
    const int wmh = wid >> 2;         // 0..1 : m half (32 rows)
    const int wn = wid & 3;           // 0..3 : n quarter (24 cols)
    const int grp = lane >> 2;        // 0..7
    const int tig = lane & 3;         // 0..3
    const int n0 = blockIdx.x * BN;
    const int m0 = blockIdx.y * BM;

    float acc[2][NTW][4];
#pragma unroll
    for (int i = 0; i < 2; i++)
#pragma unroll
        for (int j = 0; j < NTW; j++)
#pragma unroll
            for (int r = 0; r < 4; r++) acc[i][j][r] = 0.0f;

    const float4 fz = make_float4(0.f, 0.f, 0.f, 0.f);
    float4 ra, rb0, rb1;

    // ---- per-thread hoisted gmem pointers (advance += 16 per stage) ----
    const int rowT = tid >> 2;               // 0..63
    const int k4t = (tid & 3) * 4;
    const float* pA = emb + (size_t)doc[m0 + rowT] * 300 + k4t;   // direct gather
    const bool hasB1 = tid < 128;            // covers B rows 64..95
    const int rowB1 = 64 + rowT;
    const bool gokB0 = (n0 + rowT) < D_COLS;
    const bool gokB1 = hasB1 && ((n0 + rowB1) < D_COLS);
    const float* pB0 = diags + (size_t)(n0 + rowT) * 300 + k4t;
    const float* pB1 = diags + (size_t)(n0 + (hasB1 ? rowB1 : rowT)) * 300 + k4t;

    // ---- prologue: stage 0 load + convert + store ----
    {
        bool kok = k4t < 300;
        ra  = kok ? *(const float4*)pA : fz;
        rb0 = (kok && gokB0) ? *(const float4*)pB0 : fz;
        rb1 = (kok && gokB1) ? *(const float4*)pB1 : fz;
        pA += 16; pB0 += 16; pB1 += 16;
    }
    {
        unsigned h01, m01, h23, m23;
        bsplit2(ra.x, ra.y, h01, m01);
        bsplit2(ra.z, ra.w, h23, m23);
        *(uint4*)(Abuf[0] + rowT * RSTRIDE + k4t) = make_uint4(h01, m01, h23, m23);
        bsplit2(rb0.x, rb0.y, h01, m01);
        bsplit2(rb0.z, rb0.w, h23, m23);
        *(uint4*)(Bbuf[0] + rowT * RSTRIDE + k4t) = make_uint4(h01, m01, h23, m23);
        if (hasB1) {
            bsplit2(rb1.x, rb1.y, h01, m01);
            bsplit2(rb1.z, rb1.w, h23, m23);
            *(uint4*)(Bbuf[0] + rowB1 * RSTRIDE + k4t) = make_uint4(h01, m01, h23, m23);
        }
    }
    __syncthreads();

    for (int c = 0; c < NKS; c++) {
        // prefetch next stage into registers
        if (c + 1 < NKS) {
            const bool kok = ((c + 1) * 16 + k4t) < 300;
            ra  = kok ? *(const float4*)pA : fz;
            rb0 = (kok && gokB0) ? *(const float4*)pB0 : fz;
            rb1 = (kok && gokB1) ? *(const float4*)pB1 : fz;
            pA += 16; pB0 += 16; pB1 += 16;
        }
        // ---- compute: pure LDS.64 + HMMA (round-8 schedule) ----
        {
            const unsigned* As = Abuf[c & 1];
            const unsigned* Bs = Bbuf[c & 1];
            unsigned bh[NTW][2], bm[NTW][2];
#pragma unroll
            for (int nt = 0; nt < NTW; nt++) {
                const unsigned* p = Bs + (wn * 24 + nt * 8 + grp) * RSTRIDE + tig * 2;
                uint2 v0 = *(const uint2*)p;         // k-pair tig
                uint2 v1 = *(const uint2*)(p + 8);   // k-pair tig+4
                bh[nt][0] = v0.x; bm[nt][0] = v0.y;
                bh[nt][1] = v1.x; bm[nt][1] = v1.y;
            }
#pragma unroll
            for (int mt = 0; mt < 2; mt++) {
                const unsigned* p = As + (wmh * 32 + mt * 16 + grp) * RSTRIDE + tig * 2;
                uint2 a0 = *(const uint2*)p;
                uint2 a1 = *(const uint2*)(p + 8 * RSTRIDE);
                uint2 a2 = *(const uint2*)(p + 8);
                uint2 a3 = *(const uint2*)(p + 8 * RSTRIDE + 8);
                unsigned ah[4] = { a0.x, a1.x, a2.x, a3.x };
                unsigned am[4] = { a0.y, a1.y, a2.y, a3.y };
#pragma unroll
                for (int nt = 0; nt < NTW; nt++) {
                    mma_bf16(acc[mt][nt], ah, bh[nt]);
                    mma_bf16(acc[mt][nt], am, bh[nt]);
                    mma_bf16(acc[mt][nt], ah, bm[nt]);
                }
            }
        }
        // ---- convert + store prefetched stage ----
        if (c + 1 < NKS) {
            unsigned* An = Abuf[(c + 1) & 1];
            unsigned* Bn = Bbuf[(c + 1) & 1];
            unsigned h01, m01, h23, m23;
            bsplit2(ra.x, ra.y, h01, m01);
            bsplit2(ra.z, ra.w, h23, m23);
            *(uint4*)(An + rowT * RSTRIDE + k4t) = make_uint4(h01, m01, h23, m23);
            bsplit2(rb0.x, rb0.y, h01, m01);
            bsplit2(rb0.z, rb0.w, h23, m23);
            *(uint4*)(Bn + rowT * RSTRIDE + k4t) = make_uint4(h01, m01, h23, m23);
            if (hasB1) {
                bsplit2(rb1.x, rb1.y, h01, m01);
                bsplit2(rb1.z, rb1.w, h23, m23);
                *(uint4*)(Bn + rowB1 * RSTRIDE + k4t) = make_uint4(h01, m01, h23, m23);
            }
        }
        __syncthreads();
    }

    // ---- epilogue: single pass via smem (64 x 100), coalesced stores ----
    float* smep = (float*)sm;   // 64*100*4 = 25600 B <= 30720 B (buffers dead)
#pragma unroll
    for (int mt = 0; mt < 2; mt++) {
        const int r0 = wmh * 32 + mt * 16 + grp;
#pragma unroll
        for (int nt = 0; nt < NTW; nt++) {
            const int cb = wn * 24 + nt * 8 + 2 * tig;
            smep[r0 * 100 + cb]           = acc[mt][nt][0];
            smep[r0 * 100 + cb + 1]       = acc[mt][nt][1];
            smep[(r0 + 8) * 100 + cb]     = acc[mt][nt][2];
            smep[(r0 + 8) * 100 + cb + 1] = acc[mt][nt][3];
        }
    }
    __syncthreads();
#pragma unroll
    for (int i = 0; i < 6; i++) {
        int slot = tid + i * 256;             // 1536 float4 slots (64 rows x 24)
        int r = slot / 24;
        int c4 = (slot % 24) * 4;
        int gn = n0 + c4;
        if (gn < D_COLS) {                    // 2700 % 4 == 0 -> whole-float4 validity
            float4 bv = *(const float4*)(bias + gn);
            float4 o;
            o.x = 1.0f / (1.0f + __expf(-(smep[r * 100 + c4]     + bv.x)));
            o.y = 1.0f / (1.0f + __expf(-(smep[r * 100 + c4 + 1] + bv.y)));
            o.z = 1.0f / (1.0f + __expf(-(smep[r * 100 + c4 + 2] + bv.z)));
            o.w = 1.0f / (1.0f + __expf(-(smep[r * 100 + c4 + 3] + bv.w)));
            *(float4*)(g_tm + (size_t)(m0 + r) * D_COLS + gn) = o;
        }
    }
}

// =======================================================================
// Kernel 2: chunked parallel scan (unchanged)
// =======================================================================
template <int P>
__device__ __forceinline__ void scan_impl(
    const float* __restrict__ eps_raw,
    float eps_sc, float sls,
    int groupStart, int scoreOff, int chunk)
{
    const int n = threadIdx.x;
    if (n >= 50) return;

    float eps[P - 1];
#pragma unroll
    for (int j = 0; j < P - 1; j++)
        eps[j] = eps_sc * sigmoidf(eps_raw[n * (P - 1) + j]);

    const float* base = g_tm + groupStart + n * 2 * P;

    const int acc_start = chunk * CH;
    int t_begin = acc_start - WARM;
    if (t_begin < 0) t_begin = 0;
    const int t_end = acc_start + CH;
    const int nsteps = t_end - t_begin;

    constexpr int DEPTH = 8;
    float2 buf[DEPTH][P];

#pragma unroll
    for (int d = 0; d < DEPTH; d++) {
        const float2* rp = (const float2*)(base + (size_t)(t_begin + d) * D_COLS);
#pragma unroll
        for (int j = 0; j < P; j++) buf[d][j] = rp[j];
    }

    float h[P];
    h[0] = 1.0f;
#pragma unroll
    for (int i = 1; i < P; i++) h[i] = 0.0f;
    float sc = 0.0f;

    for (int sb2 = 0; sb2 < nsteps; sb2 += DEPTH) {
#pragma unroll
        for (int d = 0; d < DEPTH; d++) {
            const int t = t_begin + sb2 + d;
            float v[2 * P];
#pragma unroll
            for (int j = 0; j < P; j++) {
                v[2 * j]     = buf[d][j].x;
                v[2 * j + 1] = buf[d][j].y;
            }
            const int tn = t + DEPTH;
            if (tn < t_end) {
                const float2* rp = (const float2*)(base + (size_t)tn * D_COLS);
#pragma unroll
                for (int j = 0; j < P; j++) buf[d][j] = rp[j];
            }
#pragma unroll
            for (int i = P - 1; i >= 1; --i)
                h[i] = fmaf(h[i - 1], eps[i - 1], h[i]);
            float res[P];
            res[0] = fmaf(sls * h[0], v[0], 1.0f);
#pragma unroll
            for (int i = 1; i < P; i++)
                res[i] = fmaf(h[i - 1], v[P + i - 1], sls * h[i] * v[i]);
            if (t >= acc_start) sc += res[P - 1];
#pragma unroll
            for (int i = 0; i < P; i++) h[i] = res[i];
        }
    }
    g_part[(scoreOff + n) * NCHUNK + chunk] = sc;
}

__global__ __launch_bounds__(64) void scan_all_kernel(
    const float* e2, const float* e3, const float* e4,
    const float* e5, const float* e6, const float* e7,
    const float* __restrict__ eps_scale,
    const float* __restrict__ sls_scale)
{
    const float eps_sc = sigmoidf(eps_scale[0]);
    const float sls = sigmoidf(sls_scale[0]);
    const int chunk = blockIdx.y;
    switch (blockIdx.x) {
        case 0: scan_impl<2>(e2, eps_sc, sls,    0,   0, chunk); break;
        case 1: scan_impl<3>(e3, eps_sc, sls,  200,  50, chunk); break;
        case 2: scan_impl<4>(e4, eps_sc, sls,  500, 100, chunk); break;
        case 3: scan_impl<5>(e5, eps_sc, sls,  900, 150, chunk); break;
        case 4: scan_impl<6>(e6, eps_sc, sls, 1400, 200, chunk); break;
        case 5: scan_impl<7>(e7, eps_sc, sls, 2000, 250, chunk); break;
    }
}

// ---------------- Kernel 3: partial reduction + tiny MLP head ----------------
__global__ __launch_bounds__(128) void mlp_kernel(
    const float* __restrict__ w1, const float* __restrict__ b1,
    const float* __restrict__ w2, const float* __restrict__ b2,
    float* __restrict__ out)
{
    __shared__ float ssc[300];
    __shared__ float hsh[128];
    const int k = threadIdx.x;

    for (int j = k; j < 300; j += 128) {
        float a = 0.0f;
#pragma unroll
        for (int c = 0; c < NCHUNK; c++) a += g_part[j * NCHUNK + c];
        ssc[j] = a;
    }
    __syncthreads();

    float acc = 0.0f;
    if (k < 100) {
        acc = b1[k];
        for (int j = 0; j < 300; j++)
            acc = fmaf(ssc[j], w1[j * 100 + k], acc);
        acc = fmaxf(acc, 0.0f);
    }
    hsh[k] = (k < 100) ? acc : 0.0f;
    __syncthreads();
    if (k < 2) {
        float o = b2[k];
        for (int i = 0; i < 100; i++)
            o = fmaf(hsh[i], w2[i * 2 + k], o);
        out[k] = o;
    }
}

// ---------------- Launch ----------------
extern "C" void kernel_launch(void* const* d_in, const int* in_sizes, int n_in,
                              void* d_out, int out_size)
{
    const int*   doc       = (const int*)  d_in[0];
    const float* emb       = (const float*)d_in[1];
    const float* diags     = (const float*)d_in[2];
    const float* bias      = (const float*)d_in[3];
    const float* e2        = (const float*)d_in[4];
    const float* e3        = (const float*)d_in[5];
    const float* e4        = (const float*)d_in[6];
    const float* e5        = (const float*)d_in[7];
    const float* e6        = (const float*)d_in[8];
    const float* e7        = (const float*)d_in[9];
    const float* eps_scale = (const float*)d_in[10];
    const float* sls_scale = (const float*)d_in[11];
    const float* w1        = (const float*)d_in[12];
    const float* b1        = (const float*)d_in[13];
    const float* w2        = (const float*)d_in[14];
    const float* b2        = (const float*)d_in[15];
    float* out = (float*)d_out;

    gemm_mma_kernel<<<dim3((D_COLS + BN - 1) / BN, T_LEN / BM), 256, SMEM_BYTES>>>(doc, emb, diags, bias);
    scan_all_kernel<<<dim3(6, NCHUNK), 64>>>(e2, e3, e4, e5, e6, e7, eps_scale, sls_scale);
    mlp_kernel<<<1, 128>>>(w1, b1, w2, b2, out);
}

// round 13
// speedup vs baseline: 1.4769x; 1.1867x over previous
#include <cuda_runtime.h>
#include <math.h>

// ---------------- Scratch (no runtime allocation allowed) ----------------
#define T_LEN 2048
#define D_COLS 2700
#define CH 128
#define WARM 128
#define NCHUNK (T_LEN / CH)         // 16
__device__ __align__(16) float g_tm[T_LEN * D_COLS];
__device__ float g_part[300 * NCHUNK];

// Pre-split operands: interleaved (bf16x2 hi, bf16x2 mid) per k-pair.
// Row = 304 k = 152 uint2 = 76 uint4 (1216 B).
#define KSLOT 76
#define BROWS 2784                   // 29 tiles x 96, zero-padded beyond 2700
__device__ __align__(16) uint4 g_Apre[2048 * KSLOT];   // gathered emb[doc], split
__device__ __align__(16) uint4 g_Bpre[BROWS * KSLOT];  // diags, split

__device__ __forceinline__ float sigmoidf(float x) {
    return 1.0f / (1.0f + expf(-x));
}

// split x,y (k-even, k-odd) into packed bf16 hi-pair and mid-pair
__device__ __forceinline__ void bsplit2(float x, float y, unsigned& hp, unsigned& mp) {
    asm("cvt.rn.bf16x2.f32 %0, %1, %2;" : "=r"(hp) : "f"(y), "f"(x));
    float hx = __uint_as_float(hp << 16);
    float hy = __uint_as_float(hp & 0xFFFF0000u);
    asm("cvt.rn.bf16x2.f32 %0, %1, %2;" : "=r"(mp) : "f"(y - hy), "f"(x - hx));
}

__device__ __forceinline__ void mma_bf16(float* c, const unsigned* a, const unsigned* b) {
    asm volatile("mma.sync.aligned.m16n8k16.row.col.f32.bf16.bf16.f32 "
        "{%0,%1,%2,%3}, {%4,%5,%6,%7}, {%8,%9}, {%0,%1,%2,%3};"
        : "+f"(c[0]), "+f"(c[1]), "+f"(c[2]), "+f"(c[3])
        : "r"(a[0]), "r"(a[1]), "r"(a[2]), "r"(a[3]), "r"(b[0]), "r"(b[1]));
}

// =======================================================================
// Kernel 0: gather + split conversion (once, outside the GEMM hot loop)
// =======================================================================
__global__ __launch_bounds__(256) void preconv_kernel(
    const int* __restrict__ doc,
    const float* __restrict__ emb,
    const float* __restrict__ diags)
{
    const int idx = blockIdx.x * 256 + threadIdx.x;
    const int totalA = 2048 * KSLOT;
    const int totalB = BROWS * KSLOT;
    float4 v = make_float4(0.f, 0.f, 0.f, 0.f);
    if (idx < totalA) {
        int row = idx / KSLOT, s = idx - row * KSLOT, k = s * 4;
        if (k < 300) v = *(const float4*)(emb + (size_t)doc[row] * 300 + k);
        unsigned h01, m01, h23, m23;
        bsplit2(v.x, v.y, h01, m01);
        bsplit2(v.z, v.w, h23, m23);
        g_Apre[idx] = make_uint4(h01, m01, h23, m23);
    } else if (idx < totalA + totalB) {
        int j = idx - totalA;
        int row = j / KSLOT, s = j - row * KSLOT, k = s * 4;
        if (k < 300 && row < D_COLS)
            v = *(const float4*)(diags + (size_t)row * 300 + k);
        unsigned h01, m01, h23, m23;
        bsplit2(v.x, v.y, h01, m01);
        bsplit2(v.z, v.w, h23, m23);
        g_Bpre[j] = make_uint4(h01, m01, h23, m23);
    }
}

// =======================================================================
// Kernel 1: GEMM via mma.sync on pre-split bf16 + bias + sigmoid
//   CTA 64x96, BK=16, 19 stages, 8 warps (2m x 4n), warp tile 32x24.
//   Hot loop: LDG.128 -> STS.128 -> LDS.64 -> HMMA. No cvt, no predicates.
//   Terms per acc (validated order): hh, mh, hm. Bitwise == prior rounds.
// =======================================================================
#define BM 64
#define BN 96
#define NTW 3
#define NKS 19
#define RSTRIDE 24                   // smem row stride in u32 (96B): LDS.64 conflict-free
#define ABUFU32 (BM * RSTRIDE)       // 1536 u32
#define BBUFU32 (BN * RSTRIDE)       // 2304 u32
#define STAGEU32 (ABUFU32 + BBUFU32) // 3840 u32
#define SMEM_BYTES (2 * STAGEU32 * 4) // 30720 B

__global__ __launch_bounds__(256, 3) void gemm_mma_kernel(
    const float* __restrict__ bias)
{
    extern __shared__ unsigned sm[];
    unsigned* Abuf[2] = { sm,               sm + STAGEU32 };
    unsigned* Bbuf[2] = { sm + ABUFU32,     sm + STAGEU32 + ABUFU32 };

    const int tid = threadIdx.x;
    const int wid = tid >> 5;
    const int lane = tid & 31;
    const int wmh = wid >> 2;         // 0..1 : m half (32 rows)
    const int wn = wid & 3;           // 0..3 : n quarter (24 cols)
    const int grp = lane >> 2;        // 0..7
    const int tig = lane & 3;         // 0..3
    const int n0 = blockIdx.x * BN;
    const int m0 = blockIdx.y * BM;

    float acc[2][NTW][4];
#pragma unroll
    for (int i = 0; i < 2; i++)
#pragma unroll
        for (int j = 0; j < NTW; j++)
#pragma unroll
            for (int r = 0; r < 4; r++) acc[i][j][r] = 0.0f;

    // ---- hoisted gmem pointers over pre-split buffers ----
    const int rowT = tid >> 2;               // 0..63
    const int slot = tid & 3;                // uint4 slot within 64B stage-chunk
    const bool hasB1 = tid < 128;            // B rows 64..95
    const uint4* pA  = g_Apre + (size_t)(m0 + rowT) * KSLOT + slot;
    const uint4* pB0 = g_Bpre + (size_t)(n0 + rowT) * KSLOT + slot;
    const uint4* pB1 = g_Bpre + (size_t)(n0 + (hasB1 ? 64 + rowT : rowT)) * KSLOT + slot;

    // smem store offsets (u32 units), fixed per thread
    const int sA  = rowT * RSTRIDE + slot * 4;
    const int sB0 = rowT * RSTRIDE + slot * 4;
    const int sB1 = (64 + rowT) * RSTRIDE + slot * 4;

    // ---- prologue: stage 0 ----
    uint4 ra4  = pA[0];
    uint4 rb40 = pB0[0];
    uint4 rb41 = hasB1 ? pB1[0] : make_uint4(0u, 0u, 0u, 0u);
    pA += 4; pB0 += 4; pB1 += 4;
    *(uint4*)(Abuf[0] + sA)  = ra4;
    *(uint4*)(Bbuf[0] + sB0) = rb40;
    if (hasB1) *(uint4*)(Bbuf[0] + sB1) = rb41;
    __syncthreads();

    for (int c = 0; c < NKS; c++) {
        // prefetch next stage into registers (no predicates: buffers padded)
        if (c + 1 < NKS) {
            ra4  = pA[0];
            rb40 = pB0[0];
            if (hasB1) rb41 = pB1[0];
            pA += 4; pB0 += 4; pB1 += 4;
        }
        // ---- compute: pure LDS.64 + HMMA ----
        {
            const unsigned* As = Abuf[c & 1];
            const unsigned* Bs = Bbuf[c & 1];
            unsigned bh[NTW][2], bm[NTW][2];
#pragma unroll
            for (int nt = 0; nt < NTW; nt++) {
                const unsigned* p = Bs + (wn * 24 + nt * 8 + grp) * RSTRIDE + tig * 2;
                uint2 v0 = *(const uint2*)p;
                uint2 v1 = *(const uint2*)(p + 8);
                bh[nt][0] = v0.x; bm[nt][0] = v0.y;
                bh[nt][1] = v1.x; bm[nt][1] = v1.y;
            }
#pragma unroll
            for (int mt = 0; mt < 2; mt++) {
                const unsigned* p = As + (wmh * 32 + mt * 16 + grp) * RSTRIDE + tig * 2;
                uint2 a0 = *(const uint2*)p;
                uint2 a1 = *(const uint2*)(p + 8 * RSTRIDE);
                uint2 a2 = *(const uint2*)(p + 8);
                uint2 a3 = *(const uint2*)(p + 8 * RSTRIDE + 8);
                unsigned ah[4] = { a0.x, a1.x, a2.x, a3.x };
                unsigned am[4] = { a0.y, a1.y, a2.y, a3.y };
#pragma unroll
                for (int nt = 0; nt < NTW; nt++) {
                    mma_bf16(acc[mt][nt], ah, bh[nt]);
                    mma_bf16(acc[mt][nt], am, bh[nt]);
                    mma_bf16(acc[mt][nt], ah, bm[nt]);
                }
            }
        }
        // ---- store prefetched stage ----
        if (c + 1 < NKS) {
            unsigned* An = Abuf[(c + 1) & 1];
            unsigned* Bn = Bbuf[(c + 1) & 1];
            *(uint4*)(An + sA)  = ra4;
            *(uint4*)(Bn + sB0) = rb40;
            if (hasB1) *(uint4*)(Bn + sB1) = rb41;
        }
        __syncthreads();
    }

    // ---- epilogue: via smem (64 x 100), coalesced stores ----
    float* smep = (float*)sm;   // 25600 B (buffers dead)
#pragma unroll
    for (int mt = 0; mt < 2; mt++) {
        const int r0 = wmh * 32 + mt * 16 + grp;
#pragma unroll
        for (int nt = 0; nt < NTW; nt++) {
            const int cb = wn * 24 + nt * 8 + 2 * tig;
            smep[r0 * 100 + cb]           = acc[mt][nt][0];
            smep[r0 * 100 + cb + 1]       = acc[mt][nt][1];
            smep[(r0 + 8) * 100 + cb]     = acc[mt][nt][2];
            smep[(r0 + 8) * 100 + cb + 1] = acc[mt][nt][3];
        }
    }
    __syncthreads();
#pragma unroll
    for (int i = 0; i < 6; i++) {
        int slot2 = tid + i * 256;            // 1536 float4 slots (64 rows x 24)
        int r = slot2 / 24;
        int c4 = (slot2 % 24) * 4;
        int gn = n0 + c4;
        if (gn < D_COLS) {                    // 2700 % 4 == 0 -> whole-float4 validity
            float4 bv = *(const float4*)(bias + gn);
            float4 o;
            o.x = 1.0f / (1.0f + __expf(-(smep[r * 100 + c4]     + bv.x)));
            o.y = 1.0f / (1.0f + __expf(-(smep[r * 100 + c4 + 1] + bv.y)));
            o.z = 1.0f / (1.0f + __expf(-(smep[r * 100 + c4 + 2] + bv.z)));
            o.w = 1.0f / (1.0f + __expf(-(smep[r * 100 + c4 + 3] + bv.w)));
            *(float4*)(g_tm + (size_t)(m0 + r) * D_COLS + gn) = o;
        }
    }
}

// =======================================================================
// Kernel 2: chunked parallel scan (unchanged)
// =======================================================================
template <int P>
__device__ __forceinline__ void scan_impl(
    const float* __restrict__ eps_raw,
    float eps_sc, float sls,
    int groupStart, int scoreOff, int chunk)
{
    const int n = threadIdx.x;
    if (n >= 50) return;

    float eps[P - 1];
#pragma unroll
    for (int j = 0; j < P - 1; j++)
        eps[j] = eps_sc * sigmoidf(eps_raw[n * (P - 1) + j]);

    const float* base = g_tm + groupStart + n * 2 * P;

    const int acc_start = chunk * CH;
    int t_begin = acc_start - WARM;
    if (t_begin < 0) t_begin = 0;
    const int t_end = acc_start + CH;
    const int nsteps = t_end - t_begin;

    constexpr int DEPTH = 8;
    float2 buf[DEPTH][P];

#pragma unroll
    for (int d = 0; d < DEPTH; d++) {
        const float2* rp = (const float2*)(base + (size_t)(t_begin + d) * D_COLS);
#pragma unroll
        for (int j = 0; j < P; j++) buf[d][j] = rp[j];
    }

    float h[P];
    h[0] = 1.0f;
#pragma unroll
    for (int i = 1; i < P; i++) h[i] = 0.0f;
    float sc = 0.0f;

    for (int sb2 = 0; sb2 < nsteps; sb2 += DEPTH) {
#pragma unroll
        for (int d = 0; d < DEPTH; d++) {
            const int t = t_begin + sb2 + d;
            float v[2 * P];
#pragma unroll
            for (int j = 0; j < P; j++) {
                v[2 * j]     = buf[d][j].x;
                v[2 * j + 1] = buf[d][j].y;
            }
            const int tn = t + DEPTH;
            if (tn < t_end) {
                const float2* rp = (const float2*)(base + (size_t)tn * D_COLS);
#pragma unroll
                for (int j = 0; j < P; j++) buf[d][j] = rp[j];
            }
#pragma unroll
            for (int i = P - 1; i >= 1; --i)
                h[i] = fmaf(h[i - 1], eps[i - 1], h[i]);
            float res[P];
            res[0] = fmaf(sls * h[0], v[0], 1.0f);
#pragma unroll
            for (int i = 1; i < P; i++)
                res[i] = fmaf(h[i - 1], v[P + i - 1], sls * h[i] * v[i]);
            if (t >= acc_start) sc += res[P - 1];
#pragma unroll
            for (int i = 0; i < P; i++) h[i] = res[i];
        }
    }
    g_part[(scoreOff + n) * NCHUNK + chunk] = sc;
}

__global__ __launch_bounds__(64) void scan_all_kernel(
    const float* e2, const float* e3, const float* e4,
    const float* e5, const float* e6, const float* e7,
    const float* __restrict__ eps_scale,
    const float* __restrict__ sls_scale)
{
    const float eps_sc = sigmoidf(eps_scale[0]);
    const float sls = sigmoidf(sls_scale[0]);
    const int chunk = blockIdx.y;
    switch (blockIdx.x) {
        case 0: scan_impl<2>(e2, eps_sc, sls,    0,   0, chunk); break;
        case 1: scan_impl<3>(e3, eps_sc, sls,  200,  50, chunk); break;
        case 2: scan_impl<4>(e4, eps_sc, sls,  500, 100, chunk); break;
        case 3: scan_impl<5>(e5, eps_sc, sls,  900, 150, chunk); break;
        case 4: scan_impl<6>(e6, eps_sc, sls, 1400, 200, chunk); break;
        case 5: scan_impl<7>(e7, eps_sc, sls, 2000, 250, chunk); break;
    }
}

// ---------------- Kernel 3: partial reduction + tiny MLP head ----------------
__global__ __launch_bounds__(128) void mlp_kernel(
    const float* __restrict__ w1, const float* __restrict__ b1,
    const float* __restrict__ w2, const float* __restrict__ b2,
    float* __restrict__ out)
{
    __shared__ float ssc[300];
    __shared__ float hsh[128];
    const int k = threadIdx.x;

    for (int j = k; j < 300; j += 128) {
        float a = 0.0f;
#pragma unroll
        for (int c = 0; c < NCHUNK; c++) a += g_part[j * NCHUNK + c];
        ssc[j] = a;
    }
    __syncthreads();

    float acc = 0.0f;
    if (k < 100) {
        acc = b1[k];
        for (int j = 0; j < 300; j++)
            acc = fmaf(ssc[j], w1[j * 100 + k], acc);
        acc = fmaxf(acc, 0.0f);
    }
    hsh[k] = (k < 100) ? acc : 0.0f;
    __syncthreads();
    if (k < 2) {
        float o = b2[k];
        for (int i = 0; i < 100; i++)
            o = fmaf(hsh[i], w2[i * 2 + k], o);
        out[k] = o;
    }
}

// ---------------- Launch ----------------
extern "C" void kernel_launch(void* const* d_in, const int* in_sizes, int n_in,
                              void* d_out, int out_size)
{
    const int*   doc       = (const int*)  d_in[0];
    const float* emb       = (const float*)d_in[1];
    const float* diags     = (const float*)d_in[2];
    const float* bias      = (const float*)d_in[3];
    const float* e2        = (const float*)d_in[4];
    const float* e3        = (const float*)d_in[5];
    const float* e4        = (const float*)d_in[6];
    const float* e5        = (const float*)d_in[7];
    const float* e6        = (const float*)d_in[8];
    const float* e7        = (const float*)d_in[9];
    const float* eps_scale = (const float*)d_in[10];
    const float* sls_scale = (const float*)d_in[11];
    const float* w1        = (const float*)d_in[12];
    const float* b1        = (const float*)d_in[13];
    const float* w2        = (const float*)d_in[14];
    const float* b2        = (const float*)d_in[15];
    float* out = (float*)d_out;

    const int totalPre = 2048 * KSLOT + BROWS * KSLOT;
    preconv_kernel<<<(totalPre + 255) / 256, 256>>>(doc, emb, diags);
    gemm_mma_kernel<<<dim3((D_COLS + BN - 1) / BN, T_LEN / BM), 256, SMEM_BYTES>>>(bias);
    scan_all_kernel<<<dim3(6, NCHUNK), 64>>>(e2, e3, e4, e5, e6, e7, eps_scale, sls_scale);
    mlp_kernel<<<1, 128>>>(w1, b1, w2, b2, out);
}

// round 15
// speedup vs baseline: 1.4998x; 1.0155x over previous
#include <cuda_runtime.h>
#include <math.h>

// ---------------- Scratch (no runtime allocation allowed) ----------------
#define T_LEN 2048
#define D_COLS 2700
#define CH 64
#define WARM 128
#define NCHUNK (T_LEN / CH)         // 32
__device__ __align__(16) float g_tm[T_LEN * D_COLS];
__device__ float g_part[300 * NCHUNK];

// Pre-split operands: interleaved (bf16x2 hi, bf16x2 mid) per k-pair.
// Row = 304 k = 152 uint2 = 76 uint4 (1216 B).
#define KSLOT 76
#define BROWS 2784                   // 29 tiles x 96, zero-padded beyond 2700
__device__ __align__(16) uint4 g_Apre[2048 * KSLOT];   // gathered emb[doc], split
__device__ __align__(16) uint4 g_Bpre[BROWS * KSLOT];  // diags, split

__device__ __forceinline__ float sigmoidf(float x) {
    return 1.0f / (1.0f + expf(-x));
}

// split x,y (k-even, k-odd) into packed bf16 hi-pair and mid-pair
__device__ __forceinline__ void bsplit2(float x, float y, unsigned& hp, unsigned& mp) {
    asm("cvt.rn.bf16x2.f32 %0, %1, %2;" : "=r"(hp) : "f"(y), "f"(x));
    float hx = __uint_as_float(hp << 16);
    float hy = __uint_as_float(hp & 0xFFFF0000u);
    asm("cvt.rn.bf16x2.f32 %0, %1, %2;" : "=r"(mp) : "f"(y - hy), "f"(x - hx));
}

__device__ __forceinline__ void mma_bf16(float* c, const unsigned* a, const unsigned* b) {
    asm volatile("mma.sync.aligned.m16n8k16.row.col.f32.bf16.bf16.f32 "
        "{%0,%1,%2,%3}, {%4,%5,%6,%7}, {%8,%9}, {%0,%1,%2,%3};"
        : "+f"(c[0]), "+f"(c[1]), "+f"(c[2]), "+f"(c[3])
        : "r"(a[0]), "r"(a[1]), "r"(a[2]), "r"(a[3]), "r"(b[0]), "r"(b[1]));
}

// =======================================================================
// Kernel 0: gather + split conversion (once, outside the GEMM hot loop)
// =======================================================================
__global__ __launch_bounds__(256) void preconv_kernel(
    const int* __restrict__ doc,
    const float* __restrict__ emb,
    const float* __restrict__ diags)
{
    const int idx = blockIdx.x * 256 + threadIdx.x;
    const int totalA = 2048 * KSLOT;
    const int totalB = BROWS * KSLOT;
    float4 v = make_float4(0.f, 0.f, 0.f, 0.f);
    if (idx < totalA) {
        int row = idx / KSLOT, s = idx - row * KSLOT, k = s * 4;
        if (k < 300) v = *(const float4*)(emb + (size_t)doc[row] * 300 + k);
        unsigned h01, m01, h23, m23;
        bsplit2(v.x, v.y, h01, m01);
        bsplit2(v.z, v.w, h23, m23);
        g_Apre[idx] = make_uint4(h01, m01, h23, m23);
    } else if (idx < totalA + totalB) {
        int j = idx - totalA;
        int row = j / KSLOT, s = j - row * KSLOT, k = s * 4;
        if (k < 300 && row < D_COLS)
            v = *(const float4*)(diags + (size_t)row * 300 + k);
        unsigned h01, m01, h23, m23;
        bsplit2(v.x, v.y, h01, m01);
        bsplit2(v.z, v.w, h23, m23);
        g_Bpre[j] = make_uint4(h01, m01, h23, m23);
    }
}

// =======================================================================
// Kernel 1: GEMM via mma.sync on pre-split bf16 + bias + sigmoid
//   CTA 64x96, BK=16, 19 stages, 8 warps (2m x 4n), warp tile 32x24.
//   Hot loop: LDG.128 -> STS.128 -> LDS.64 -> HMMA. No cvt, no predicates.
// =======================================================================
#define BM 64
#define BN 96
#define NTW 3
#define NKS 19
#define RSTRIDE 24                   // smem row stride in u32 (96B): LDS.64 conflict-free
#define ABUFU32 (BM * RSTRIDE)       // 1536 u32
#define BBUFU32 (BN * RSTRIDE)       // 2304 u32
#define STAGEU32 (ABUFU32 + BBUFU32) // 3840 u32
#define SMEM_BYTES (2 * STAGEU32 * 4) // 30720 B

__global__ __launch_bounds__(256, 3) void gemm_mma_kernel(
    const float* __restrict__ bias)
{
    extern __shared__ unsigned sm[];
    unsigned* Abuf[2] = { sm,               sm + STAGEU32 };
    unsigned* Bbuf[2] = { sm + ABUFU32,     sm + STAGEU32 + ABUFU32 };

    const int tid = threadIdx.x;
    const int wid = tid >> 5;
    const int lane = tid & 31;
    const int wmh = wid >> 2;         // 0..1 : m half (32 rows)
    const int wn = wid & 3;           // 0..3 : n quarter (24 cols)
    const int grp = lane >> 2;        // 0..7
    const int tig = lane & 3;         // 0..3
    const int n0 = blockIdx.x * BN;
    const int m0 = blockIdx.y * BM;

    float acc[2][NTW][4];
#pragma unroll
    for (int i = 0; i < 2; i++)
#pragma unroll
        for (int j = 0; j < NTW; j++)
#pragma unroll
            for (int r = 0; r < 4; r++) acc[i][j][r] = 0.0f;

    // ---- hoisted gmem pointers over pre-split buffers ----
    const int rowT = tid >> 2;               // 0..63
    const int slot = tid & 3;                // uint4 slot within 64B stage-chunk
    const bool hasB1 = tid < 128;            // B rows 64..95
    const uint4* pA  = g_Apre + (size_t)(m0 + rowT) * KSLOT + slot;
    const uint4* pB0 = g_Bpre + (size_t)(n0 + rowT) * KSLOT + slot;
    const uint4* pB1 = g_Bpre + (size_t)(n0 + (hasB1 ? 64 + rowT : rowT)) * KSLOT + slot;

    // smem store offsets (u32 units), fixed per thread
    const int sA  = rowT * RSTRIDE + slot * 4;
    const int sB0 = rowT * RSTRIDE + slot * 4;
    const int sB1 = (64 + rowT) * RSTRIDE + slot * 4;

    // ---- prologue: stage 0 ----
    uint4 ra4  = pA[0];
    uint4 rb40 = pB0[0];
    uint4 rb41 = hasB1 ? pB1[0] : make_uint4(0u, 0u, 0u, 0u);
    pA += 4; pB0 += 4; pB1 += 4;
    *(uint4*)(Abuf[0] + sA)  = ra4;
    *(uint4*)(Bbuf[0] + sB0) = rb40;
    if (hasB1) *(uint4*)(Bbuf[0] + sB1) = rb41;
    __syncthreads();

    for (int c = 0; c < NKS; c++) {
        // prefetch next stage into registers (no predicates: buffers padded)
        if (c + 1 < NKS) {
            ra4  = pA[0];
            rb40 = pB0[0];
            if (hasB1) rb41 = pB1[0];
            pA += 4; pB0 += 4; pB1 += 4;
        }
        // ---- compute: pure LDS.64 + HMMA ----
        {
            const unsigned* As = Abuf[c & 1];
            const unsigned* Bs = Bbuf[c & 1];
            unsigned bh[NTW][2], bm[NTW][2];
#pragma unroll
            for (int nt = 0; nt < NTW; nt++) {
                const unsigned* p = Bs + (wn * 24 + nt * 8 + grp) * RSTRIDE + tig * 2;
                uint2 v0 = *(const uint2*)p;
                uint2 v1 = *(const uint2*)(p + 8);
                bh[nt][0] = v0.x; bm[nt][0] = v0.y;
                bh[nt][1] = v1.x; bm[nt][1] = v1.y;
            }
#pragma unroll
            for (int mt = 0; mt < 2; mt++) {
                const unsigned* p = As + (wmh * 32 + mt * 16 + grp) * RSTRIDE + tig * 2;
                uint2 a0 = *(const uint2*)p;
                uint2 a1 = *(const uint2*)(p + 8 * RSTRIDE);
                uint2 a2 = *(const uint2*)(p + 8);
                uint2 a3 = *(const uint2*)(p + 8 * RSTRIDE + 8);
                unsigned ah[4] = { a0.x, a1.x, a2.x, a3.x };
                unsigned am[4] = { a0.y, a1.y, a2.y, a3.y };
#pragma unroll
                for (int nt = 0; nt < NTW; nt++) {
                    mma_bf16(acc[mt][nt], ah, bh[nt]);
                    mma_bf16(acc[mt][nt], am, bh[nt]);
                    mma_bf16(acc[mt][nt], ah, bm[nt]);
                }
            }
        }
        // ---- store prefetched stage ----
        if (c + 1 < NKS) {
            unsigned* An = Abuf[(c + 1) & 1];
            unsigned* Bn = Bbuf[(c + 1) & 1];
            *(uint4*)(An + sA)  = ra4;
            *(uint4*)(Bn + sB0) = rb40;
            if (hasB1) *(uint4*)(Bn + sB1) = rb41;
        }
        __syncthreads();
    }

    // ---- epilogue: via smem (64 x 100), coalesced stores ----
    float* smep = (float*)sm;   // 25600 B (buffers dead)
#pragma unroll
    for (int mt = 0; mt < 2; mt++) {
        const int r0 = wmh * 32 + mt * 16 + grp;
#pragma unroll
        for (int nt = 0; nt < NTW; nt++) {
            const int cb = wn * 24 + nt * 8 + 2 * tig;
            smep[r0 * 100 + cb]           = acc[mt][nt][0];
            smep[r0 * 100 + cb + 1]       = acc[mt][nt][1];
            smep[(r0 + 8) * 100 + cb]     = acc[mt][nt][2];
            smep[(r0 + 8) * 100 + cb + 1] = acc[mt][nt][3];
        }
    }
    __syncthreads();
#pragma unroll
    for (int i = 0; i < 6; i++) {
        int slot2 = tid + i * 256;            // 1536 float4 slots (64 rows x 24)
        int r = slot2 / 24;
        int c4 = (slot2 % 24) * 4;
        int gn = n0 + c4;
        if (gn < D_COLS) {                    // 2700 % 4 == 0 -> whole-float4 validity
            float4 bv = *(const float4*)(bias + gn);
            float4 o;
            o.x = 1.0f / (1.0f + __expf(-(smep[r * 100 + c4]     + bv.x)));
            o.y = 1.0f / (1.0f + __expf(-(smep[r * 100 + c4 + 1] + bv.y)));
            o.z = 1.0f / (1.0f + __expf(-(smep[r * 100 + c4 + 2] + bv.z)));
            o.w = 1.0f / (1.0f + __expf(-(smep[r * 100 + c4 + 3] + bv.w)));
            *(float4*)(g_tm + (size_t)(m0 + r) * D_COLS + gn) = o;
        }
    }
}

// =======================================================================
// Kernel 2: chunked parallel scan (CH=64, NCHUNK=32)
//   Chunks 0-2 start exactly at t=0 (no approximation); chunks >=3 warm
//   up WARM=128 steps from the restart state.
// =======================================================================
template <int P>
__device__ __forceinline__ void scan_impl(
    const float* __restrict__ eps_raw,
    float eps_sc, float sls,
    int groupStart, int scoreOff, int chunk)
{
    const int n = threadIdx.x;
    if (n >= 50) return;

    float eps[P - 1];
#pragma unroll
    for (int j = 0; j < P - 1; j++)
        eps[j] = eps_sc * sigmoidf(eps_raw[n * (P - 1) + j]);

    const float* base = g_tm + groupStart + n * 2 * P;

    const int acc_start = chunk * CH;
    int t_begin = acc_start - WARM;
    if (t_begin < 0) t_begin = 0;
    const int t_end = acc_start + CH;
    const int nsteps = t_end - t_begin;     // 64,128,192,192,... all % 8 == 0

    constexpr int DEPTH = 8;
    float2 buf[DEPTH][P];

#pragma unroll
    for (int d = 0; d < DEPTH; d++) {
        const float2* rp = (const float2*)(base + (size_t)(t_begin + d) * D_COLS);
#pragma unroll
        for (int j = 0; j < P; j++) buf[d][j] = rp[j];
    }

    float h[P];
    h[0] = 1.0f;
#pragma unroll
    for (int i = 1; i < P; i++) h[i] = 0.0f;
    float sc = 0.0f;

    for (int sb2 = 0; sb2 < nsteps; sb2 += DEPTH) {
#pragma unroll
        for (int d = 0; d < DEPTH; d++) {
            const int t = t_begin + sb2 + d;
            float v[2 * P];
#pragma unroll
            for (int j = 0; j < P; j++) {
                v[2 * j]     = buf[d][j].x;
                v[2 * j + 1] = buf[d][j].y;
            }
            const int tn = t + DEPTH;
            if (tn < t_end) {
                const float2* rp = (const float2*)(base + (size_t)tn * D_COLS);
#pragma unroll
                for (int j = 0; j < P; j++) buf[d][j] = rp[j];
            }
#pragma unroll
            for (int i = P - 1; i >= 1; --i)
                h[i] = fmaf(h[i - 1], eps[i - 1], h[i]);
            float res[P];
            res[0] = fmaf(sls * h[0], v[0], 1.0f);
#pragma unroll
            for (int i = 1; i < P; i++)
                res[i] = fmaf(h[i - 1], v[P + i - 1], sls * h[i] * v[i]);
            if (t >= acc_start) sc += res[P - 1];
#pragma unroll
            for (int i = 0; i < P; i++) h[i] = res[i];
        }
    }
    g_part[(scoreOff + n) * NCHUNK + chunk] = sc;
}

__global__ __launch_bounds__(64) void scan_all_kernel(
    const float* e2, const float* e3, const float* e4,
    const float* e5, const float* e6, const float* e7,
    const float* __restrict__ eps_scale,
    const float* __restrict__ sls_scale)
{
    const float eps_sc = sigmoidf(eps_scale[0]);
    const float sls = sigmoidf(sls_scale[0]);
    const int chunk = blockIdx.y;
    switch (blockIdx.x) {
        case 0: scan_impl<2>(e2, eps_sc, sls,    0,   0, chunk); break;
        case 1: scan_impl<3>(e3, eps_sc, sls,  200,  50, chunk); break;
        case 2: scan_impl<4>(e4, eps_sc, sls,  500, 100, chunk); break;
        case 3: scan_impl<5>(e5, eps_sc, sls,  900, 150, chunk); break;
        case 4: scan_impl<6>(e6, eps_sc, sls, 1400, 200, chunk); break;
        case 5: scan_impl<7>(e7, eps_sc, sls, 2000, 250, chunk); break;
    }
}

// =======================================================================
// Kernel 3: partial reduction + MLP head (parallelized: 1024 threads)
//   128 k-lanes x 8 j-groups; part row is 128 wide so every tid maps to
//   a unique in-bounds word (the round-14 bug was part[8][104] overflow).
// =======================================================================
__global__ __launch_bounds__(1024) void mlp_kernel(
    const float* __restrict__ w1, const float* __restrict__ b1,
    const float* __restrict__ w2, const float* __restrict__ b2,
    float* __restrict__ out)
{
    __shared__ float ssc[300];
    __shared__ float part[8][128];
    __shared__ float hsh[100];
    const int tid = threadIdx.x;
    const int k = tid & 127;          // 0..127
    const int jg = tid >> 7;          // 0..7

    // reduce chunk partials -> scores (one j per thread)
    for (int j = tid; j < 300; j += 1024) {
        float a = 0.0f;
#pragma unroll
        for (int c = 0; c < NCHUNK; c++) a += g_part[j * NCHUNK + c];
        ssc[j] = a;
    }
    __syncthreads();

    // layer 1 partials: j-group [jg*38, min(300, jg*38+38))
    float a0 = 0.0f, a1 = 0.0f;
    if (k < 100) {
        const int j0 = jg * 38;
        const int j1 = (j0 + 38 < 300) ? j0 + 38 : 300;
        int j = j0;
        for (; j + 1 < j1; j += 2) {
            a0 = fmaf(ssc[j],     w1[j * 100 + k],       a0);
            a1 = fmaf(ssc[j + 1], w1[(j + 1) * 100 + k], a1);
        }
        if (j < j1) a0 = fmaf(ssc[j], w1[j * 100 + k], a0);
    }
    part[jg][k] = a0 + a1;
    __syncthreads();

    // tree-reduce 8 j-groups, bias + relu
    if (tid < 100) {
        float h = b1[tid];
#pragma unroll
        for (int g = 0; g < 8; g++) h += part[g][tid];
        hsh[tid] = fmaxf(h, 0.0f);
    }
    __syncthreads();

    // layer 2: two warps, one output each, shuffle-reduce
    if (tid < 64) {
        const int c = tid >> 5;
        const int l = tid & 31;
        float o = 0.0f;
        for (int i = l; i < 100; i += 32)
            o = fmaf(hsh[i], w2[i * 2 + c], o);
#pragma unroll
        for (int s = 16; s > 0; s >>= 1)
            o += __shfl_xor_sync(0xffffffffu, o, s);
        if (l == 0) out[c] = o + b2[c];
    }
}

// ---------------- Launch ----------------
extern "C" void kernel_launch(void* const* d_in, const int* in_sizes, int n_in,
                              void* d_out, int out_size)
{
    const int*   doc       = (const int*)  d_in[0];
    const float* emb       = (const float*)d_in[1];
    const float* diags     = (const float*)d_in[2];
    const float* bias      = (const float*)d_in[3];
    const float* e2        = (const float*)d_in[4];
    const float* e3        = (const float*)d_in[5];
    const float* e4        = (const float*)d_in[6];
    const float* e5        = (const float*)d_in[7];
    const float* e6        = (const float*)d_in[8];
    const float* e7        = (const float*)d_in[9];
    const float* eps_scale = (const float*)d_in[10];
    const float* sls_scale = (const float*)d_in[11];
    const float* w1        = (const float*)d_in[12];
    const float* b1        = (const float*)d_in[13];
    const float* w2        = (const float*)d_in[14];
    const float* b2        = (const float*)d_in[15];
    float* out = (float*)d_out;

    const int totalPre = 2048 * KSLOT + BROWS * KSLOT;
    preconv_kernel<<<(totalPre + 255) / 256, 256>>>(doc, emb, diags);
    gemm_mma_kernel<<<dim3((D_COLS + BN - 1) / BN, T_LEN / BM), 256, SMEM_BYTES>>>(bias);
    scan_all_kernel<<<dim3(6, NCHUNK), 64>>>(e2, e3, e4, e5, e6, e7, eps_scale, sls_scale);
    mlp_kernel<<<1, 1024>>>(w1, b1, w2, b2, out);
}

// round 16
// speedup vs baseline: 1.5849x; 1.0567x over previous
#include <cuda_runtime.h>
#include <math.h>

// ---------------- Scratch (no runtime allocation allowed) ----------------
#define T_LEN 2048
#define D_COLS 2700
#define CH 64
#define WARM 128
#define NCHUNK (T_LEN / CH)         // 32
__device__ __align__(16) float g_tm[T_LEN * D_COLS];
__device__ float g_part[NCHUNK * 300];   // [chunk][pattern] -- coalesced both ways
__device__ float g_hpart[8 * 100];       // per-block layer-1 partials

// Pre-split operands: interleaved (bf16x2 hi, bf16x2 mid) per k-pair.
#define KSLOT 76
#define BROWS 2784                   // 29 tiles x 96, zero-padded beyond 2700
__device__ __align__(16) uint4 g_Apre[2048 * KSLOT];   // gathered emb[doc], split
__device__ __align__(16) uint4 g_Bpre[BROWS * KSLOT];  // diags, split

__device__ __forceinline__ float sigmoidf(float x) {
    return 1.0f / (1.0f + expf(-x));
}

// split x,y (k-even, k-odd) into packed bf16 hi-pair and mid-pair
__device__ __forceinline__ void bsplit2(float x, float y, unsigned& hp, unsigned& mp) {
    asm("cvt.rn.bf16x2.f32 %0, %1, %2;" : "=r"(hp) : "f"(y), "f"(x));
    float hx = __uint_as_float(hp << 16);
    float hy = __uint_as_float(hp & 0xFFFF0000u);
    asm("cvt.rn.bf16x2.f32 %0, %1, %2;" : "=r"(mp) : "f"(y - hy), "f"(x - hx));
}

__device__ __forceinline__ void mma_bf16(float* c, const unsigned* a, const unsigned* b) {
    asm volatile("mma.sync.aligned.m16n8k16.row.col.f32.bf16.bf16.f32 "
        "{%0,%1,%2,%3}, {%4,%5,%6,%7}, {%8,%9}, {%0,%1,%2,%3};"
        : "+f"(c[0]), "+f"(c[1]), "+f"(c[2]), "+f"(c[3])
        : "r"(a[0]), "r"(a[1]), "r"(a[2]), "r"(a[3]), "r"(b[0]), "r"(b[1]));
}

// =======================================================================
// Kernel 0: gather + split conversion (once, outside the GEMM hot loop)
// =======================================================================
__global__ __launch_bounds__(256) void preconv_kernel(
    const int* __restrict__ doc,
    const float* __restrict__ emb,
    const float* __restrict__ diags)
{
    const int idx = blockIdx.x * 256 + threadIdx.x;
    const int totalA = 2048 * KSLOT;
    const int totalB = BROWS * KSLOT;
    float4 v = make_float4(0.f, 0.f, 0.f, 0.f);
    if (idx < totalA) {
        int row = idx / KSLOT, s = idx - row * KSLOT, k = s * 4;
        if (k < 300) v = *(const float4*)(emb + (size_t)doc[row] * 300 + k);
        unsigned h01, m01, h23, m23;
        bsplit2(v.x, v.y, h01, m01);
        bsplit2(v.z, v.w, h23, m23);
        g_Apre[idx] = make_uint4(h01, m01, h23, m23);
    } else if (idx < totalA + totalB) {
        int j = idx - totalA;
        int row = j / KSLOT, s = j - row * KSLOT, k = s * 4;
        if (k < 300 && row < D_COLS)
            v = *(const float4*)(diags + (size_t)row * 300 + k);
        unsigned h01, m01, h23, m23;
        bsplit2(v.x, v.y, h01, m01);
        bsplit2(v.z, v.w, h23, m23);
        g_Bpre[j] = make_uint4(h01, m01, h23, m23);
    }
}

// =======================================================================
// Kernel 1: GEMM via mma.sync on pre-split bf16 + bias + sigmoid
//   CTA 64x96, BK=16, 19 stages, 8 warps (2m x 4n), warp tile 32x24.
// =======================================================================
#define BM 64
#define BN 96
#define NTW 3
#define NKS 19
#define RSTRIDE 24                   // smem row stride in u32 (96B): LDS.64 conflict-free
#define ABUFU32 (BM * RSTRIDE)       // 1536 u32
#define BBUFU32 (BN * RSTRIDE)       // 2304 u32
#define STAGEU32 (ABUFU32 + BBUFU32) // 3840 u32
#define SMEM_BYTES (2 * STAGEU32 * 4) // 30720 B

__global__ __launch_bounds__(256, 3) void gemm_mma_kernel(
    const float* __restrict__ bias)
{
    extern __shared__ unsigned sm[];
    unsigned* Abuf[2] = { sm,               sm + STAGEU32 };
    unsigned* Bbuf[2] = { sm + ABUFU32,     sm + STAGEU32 + ABUFU32 };

    const int tid = threadIdx.x;
    const int wid = tid >> 5;
    const int lane = tid & 31;
    const int wmh = wid >> 2;
    const int wn = wid & 3;
    const int grp = lane >> 2;
    const int tig = lane & 3;
    const int n0 = blockIdx.x * BN;
    const int m0 = blockIdx.y * BM;

    float acc[2][NTW][4];
#pragma unroll
    for (int i = 0; i < 2; i++)
#pragma unroll
        for (int j = 0; j < NTW; j++)
#pragma unroll
            for (int r = 0; r < 4; r++) acc[i][j][r] = 0.0f;

    const int rowT = tid >> 2;
    const int slot = tid & 3;
    const bool hasB1 = tid < 128;
    const uint4* pA  = g_Apre + (size_t)(m0 + rowT) * KSLOT + slot;
    const uint4* pB0 = g_Bpre + (size_t)(n0 + rowT) * KSLOT + slot;
    const uint4* pB1 = g_Bpre + (size_t)(n0 + (hasB1 ? 64 + rowT : rowT)) * KSLOT + slot;

    const int sA  = rowT * RSTRIDE + slot * 4;
    const int sB0 = rowT * RSTRIDE + slot * 4;
    const int sB1 = (64 + rowT) * RSTRIDE + slot * 4;

    uint4 ra4  = pA[0];
    uint4 rb40 = pB0[0];
    uint4 rb41 = hasB1 ? pB1[0] : make_uint4(0u, 0u, 0u, 0u);
    pA += 4; pB0 += 4; pB1 += 4;
    *(uint4*)(Abuf[0] + sA)  = ra4;
    *(uint4*)(Bbuf[0] + sB0) = rb40;
    if (hasB1) *(uint4*)(Bbuf[0] + sB1) = rb41;
    __syncthreads();

    for (int c = 0; c < NKS; c++) {
        if (c + 1 < NKS) {
            ra4  = pA[0];
            rb40 = pB0[0];
            if (hasB1) rb41 = pB1[0];
            pA += 4; pB0 += 4; pB1 += 4;
        }
        {
            const unsigned* As = Abuf[c & 1];
            const unsigned* Bs = Bbuf[c & 1];
            unsigned bh[NTW][2], bm[NTW][2];
#pragma unroll
            for (int nt = 0; nt < NTW; nt++) {
                const unsigned* p = Bs + (wn * 24 + nt * 8 + grp) * RSTRIDE + tig * 2;
                uint2 v0 = *(const uint2*)p;
                uint2 v1 = *(const uint2*)(p + 8);
                bh[nt][0] = v0.x; bm[nt][0] = v0.y;
                bh[nt][1] = v1.x; bm[nt][1] = v1.y;
            }
#pragma unroll
            for (int mt = 0; mt < 2; mt++) {
                const unsigned* p = As + (wmh * 32 + mt * 16 + grp) * RSTRIDE + tig * 2;
                uint2 a0 = *(const uint2*)p;
                uint2 a1 = *(const uint2*)(p + 8 * RSTRIDE);
                uint2 a2 = *(const uint2*)(p + 8);
                uint2 a3 = *(const uint2*)(p + 8 * RSTRIDE + 8);
                unsigned ah[4] = { a0.x, a1.x, a2.x, a3.x };
                unsigned am[4] = { a0.y, a1.y, a2.y, a3.y };
#pragma unroll
                for (int nt = 0; nt < NTW; nt++) {
                    mma_bf16(acc[mt][nt], ah, bh[nt]);
                    mma_bf16(acc[mt][nt], am, bh[nt]);
                    mma_bf16(acc[mt][nt], ah, bm[nt]);
                }
            }
        }
        if (c + 1 < NKS) {
            unsigned* An = Abuf[(c + 1) & 1];
            unsigned* Bn = Bbuf[(c + 1) & 1];
            *(uint4*)(An + sA)  = ra4;
            *(uint4*)(Bn + sB0) = rb40;
            if (hasB1) *(uint4*)(Bn + sB1) = rb41;
        }
        __syncthreads();
    }

    // ---- epilogue: via smem (64 x 100), coalesced stores ----
    float* smep = (float*)sm;
#pragma unroll
    for (int mt = 0; mt < 2; mt++) {
        const int r0 = wmh * 32 + mt * 16 + grp;
#pragma unroll
        for (int nt = 0; nt < NTW; nt++) {
            const int cb = wn * 24 + nt * 8 + 2 * tig;
            smep[r0 * 100 + cb]           = acc[mt][nt][0];
            smep[r0 * 100 + cb + 1]       = acc[mt][nt][1];
            smep[(r0 + 8) * 100 + cb]     = acc[mt][nt][2];
            smep[(r0 + 8) * 100 + cb + 1] = acc[mt][nt][3];
        }
    }
    __syncthreads();
#pragma unroll
    for (int i = 0; i < 6; i++) {
        int slot2 = tid + i * 256;
        int r = slot2 / 24;
        int c4 = (slot2 % 24) * 4;
        int gn = n0 + c4;
        if (gn < D_COLS) {
            float4 bv = *(const float4*)(bias + gn);
            float4 o;
            o.x = 1.0f / (1.0f + __expf(-(smep[r * 100 + c4]     + bv.x)));
            o.y = 1.0f / (1.0f + __expf(-(smep[r * 100 + c4 + 1] + bv.y)));
            o.z = 1.0f / (1.0f + __expf(-(smep[r * 100 + c4 + 2] + bv.z)));
            o.w = 1.0f / (1.0f + __expf(-(smep[r * 100 + c4 + 3] + bv.w)));
            *(float4*)(g_tm + (size_t)(m0 + r) * D_COLS + gn) = o;
        }
    }
}

// =======================================================================
// Kernel 2: chunked parallel scan (CH=64, NCHUNK=32)
//   Writes g_part[chunk][pattern] (coalesced across threads).
// =======================================================================
template <int P>
__device__ __forceinline__ void scan_impl(
    const float* __restrict__ eps_raw,
    float eps_sc, float sls,
    int groupStart, int scoreOff, int chunk)
{
    const int n = threadIdx.x;
    if (n >= 50) return;

    float eps[P - 1];
#pragma unroll
    for (int j = 0; j < P - 1; j++)
        eps[j] = eps_sc * sigmoidf(eps_raw[n * (P - 1) + j]);

    const float* base = g_tm + groupStart + n * 2 * P;

    const int acc_start = chunk * CH;
    int t_begin = acc_start - WARM;
    if (t_begin < 0) t_begin = 0;
    const int t_end = acc_start + CH;
    const int nsteps = t_end - t_begin;

    constexpr int DEPTH = 8;
    float2 buf[DEPTH][P];

#pragma unroll
    for (int d = 0; d < DEPTH; d++) {
        const float2* rp = (const float2*)(base + (size_t)(t_begin + d) * D_COLS);
#pragma unroll
        for (int j = 0; j < P; j++) buf[d][j] = rp[j];
    }

    float h[P];
    h[0] = 1.0f;
#pragma unroll
    for (int i = 1; i < P; i++) h[i] = 0.0f;
    float sc = 0.0f;

    for (int sb2 = 0; sb2 < nsteps; sb2 += DEPTH) {
#pragma unroll
        for (int d = 0; d < DEPTH; d++) {
            const int t = t_begin + sb2 + d;
            float v[2 * P];
#pragma unroll
            for (int j = 0; j < P; j++) {
                v[2 * j]     = buf[d][j].x;
                v[2 * j + 1] = buf[d][j].y;
            }
            const int tn = t + DEPTH;
            if (tn < t_end) {
                const float2* rp = (const float2*)(base + (size_t)tn * D_COLS);
#pragma unroll
                for (int j = 0; j < P; j++) buf[d][j] = rp[j];
            }
#pragma unroll
            for (int i = P - 1; i >= 1; --i)
                h[i] = fmaf(h[i - 1], eps[i - 1], h[i]);
            float res[P];
            res[0] = fmaf(sls * h[0], v[0], 1.0f);
#pragma unroll
            for (int i = 1; i < P; i++)
                res[i] = fmaf(h[i - 1], v[P + i - 1], sls * h[i] * v[i]);
            if (t >= acc_start) sc += res[P - 1];
#pragma unroll
            for (int i = 0; i < P; i++) h[i] = res[i];
        }
    }
    g_part[chunk * 300 + scoreOff + n] = sc;
}

__global__ __launch_bounds__(64) void scan_all_kernel(
    const float* e2, const float* e3, const float* e4,
    const float* e5, const float* e6, const float* e7,
    const float* __restrict__ eps_scale,
    const float* __restrict__ sls_scale)
{
    const float eps_sc = sigmoidf(eps_scale[0]);
    const float sls = sigmoidf(sls_scale[0]);
    const int chunk = blockIdx.y;
    switch (blockIdx.x) {
        case 0: scan_impl<2>(e2, eps_sc, sls,    0,   0, chunk); break;
        case 1: scan_impl<3>(e3, eps_sc, sls,  200,  50, chunk); break;
        case 2: scan_impl<4>(e4, eps_sc, sls,  500, 100, chunk); break;
        case 3: scan_impl<5>(e5, eps_sc, sls,  900, 150, chunk); break;
        case 4: scan_impl<6>(e6, eps_sc, sls, 1400, 200, chunk); break;
        case 5: scan_impl<7>(e7, eps_sc, sls, 2000, 250, chunk); break;
    }
}

// =======================================================================
// Kernel 3a: layer-1 partials across 8 blocks (j-sliced, deterministic)
// =======================================================================
__global__ __launch_bounds__(256) void mlp_part_kernel(
    const float* __restrict__ w1)
{
    __shared__ float ssc[40];
    __shared__ float half1[128];
    const int b = blockIdx.x;          // 0..7
    const int j0 = b * 38;
    const int cnt = (300 - j0 < 38) ? 300 - j0 : 38;
    const int tid = threadIdx.x;

    // reduce this block's pattern slice: g_part[c][j0+tid], lanes coalesced
    if (tid < cnt) {
        float a = 0.0f;
        const float* gp = g_part + j0 + tid;
#pragma unroll
        for (int c = 0; c < NCHUNK; c++) a += gp[c * 300];
        ssc[tid] = a;
    }
    __syncthreads();

    const int k = tid & 127;           // 0..127 (k<100 active)
    const int hf = tid >> 7;           // 0..1 : j sub-half
    float a = 0.0f;
    if (k < 100) {
        const int js = hf * 19;
        const int je = (js + 19 < cnt) ? js + 19 : cnt;
        for (int j = js; j < je; j++)
            a = fmaf(ssc[j], w1[(j0 + j) * 100 + k], a);
    }
    if (hf == 1) half1[k] = a;
    __syncthreads();
    if (hf == 0 && k < 100)
        g_hpart[b * 100 + k] = a + half1[k];
}

// =======================================================================
// Kernel 3b: combine partials + relu + layer 2
// =======================================================================
__global__ __launch_bounds__(128) void mlp_final_kernel(
    const float* __restrict__ b1,
    const float* __restrict__ w2, const float* __restrict__ b2,
    float* __restrict__ out)
{
    __shared__ float hsh[100];
    const int tid = threadIdx.x;
    if (tid < 100) {
        float h = b1[tid];
#pragma unroll
        for (int g = 0; g < 8; g++) h += g_hpart[g * 100 + tid];
        hsh[tid] = fmaxf(h, 0.0f);
    }
    __syncthreads();
    if (tid < 64) {
        const int c = tid >> 5;
        const int l = tid & 31;
        float o = 0.0f;
        for (int i = l; i < 100; i += 32)
            o = fmaf(hsh[i], w2[i * 2 + c], o);
#pragma unroll
        for (int s = 16; s > 0; s >>= 1)
            o += __shfl_xor_sync(0xffffffffu, o, s);
        if (l == 0) out[c] = o + b2[c];
    }
}

// ---------------- Launch ----------------
extern "C" void kernel_launch(void* const* d_in, const int* in_sizes, int n_in,
                              void* d_out, int out_size)
{
    const int*   doc       = (const int*)  d_in[0];
    const float* emb       = (const float*)d_in[1];
    const float* diags     = (const float*)d_in[2];
    const float* bias      = (const float*)d_in[3];
    const float* e2        = (const float*)d_in[4];
    const float* e3        = (const float*)d_in[5];
    const float* e4        = (const float*)d_in[6];
    const float* e5        = (const float*)d_in[7];
    const float* e6        = (const float*)d_in[8];
    const float* e7        = (const float*)d_in[9];
    const float* eps_scale = (const float*)d_in[10];
    const float* sls_scale = (const float*)d_in[11];
    const float* w1        = (const float*)d_in[12];
    const float* b1        = (const float*)d_in[13];
    const float* w2        = (const float*)d_in[14];
    const float* b2        = (const float*)d_in[15];
    float* out = (float*)d_out;

    const int totalPre = 2048 * KSLOT + BROWS * KSLOT;
    preconv_kernel<<<(totalPre + 255) / 256, 256>>>(doc, emb, diags);
    gemm_mma_kernel<<<dim3((D_COLS + BN - 1) / BN, T_LEN / BM), 256, SMEM_BYTES>>>(bias);
    scan_all_kernel<<<dim3(6, NCHUNK), 64>>>(e2, e3, e4, e5, e6, e7, eps_scale, sls_scale);
    mlp_part_kernel<<<8, 256>>>(w1);
    mlp_final_kernel<<<1, 128>>>(b1, w2, b2, out);
}

// round 17
// speedup vs baseline: 1.6163x; 1.0198x over previous
#include <cuda_runtime.h>
#include <math.h>

// ---------------- Scratch (no runtime allocation allowed) ----------------
#define T_LEN 2048
#define D_COLS 2700
#define CH 64
#define WARM 128
#define NCHUNK (T_LEN / CH)         // 32
__device__ __align__(16) float g_tm[T_LEN * D_COLS];
__device__ float g_part[NCHUNK * 300];   // [chunk][pattern] -- coalesced both ways
#define MLPB 25                          // head blocks (300 = 25 * 12)
#define MLPJ 12                          // patterns per head block
__device__ float g_hpart[MLPB * 100];    // per-block layer-1 partials

// Pre-split operands: interleaved (bf16x2 hi, bf16x2 mid) per k-pair.
#define KSLOT 76
#define BROWS 2784                   // 29 tiles x 96, zero-padded beyond 2700
__device__ __align__(16) uint4 g_Apre[2048 * KSLOT];   // gathered emb[doc], split
__device__ __align__(16) uint4 g_Bpre[BROWS * KSLOT];  // diags, split

__device__ __forceinline__ float sigmoidf(float x) {
    return 1.0f / (1.0f + expf(-x));
}

// split x,y (k-even, k-odd) into packed bf16 hi-pair and mid-pair
__device__ __forceinline__ void bsplit2(float x, float y, unsigned& hp, unsigned& mp) {
    asm("cvt.rn.bf16x2.f32 %0, %1, %2;" : "=r"(hp) : "f"(y), "f"(x));
    float hx = __uint_as_float(hp << 16);
    float hy = __uint_as_float(hp & 0xFFFF0000u);
    asm("cvt.rn.bf16x2.f32 %0, %1, %2;" : "=r"(mp) : "f"(y - hy), "f"(x - hx));
}

__device__ __forceinline__ void mma_bf16(float* c, const unsigned* a, const unsigned* b) {
    asm volatile("mma.sync.aligned.m16n8k16.row.col.f32.bf16.bf16.f32 "
        "{%0,%1,%2,%3}, {%4,%5,%6,%7}, {%8,%9}, {%0,%1,%2,%3};"
        : "+f"(c[0]), "+f"(c[1]), "+f"(c[2]), "+f"(c[3])
        : "r"(a[0]), "r"(a[1]), "r"(a[2]), "r"(a[3]), "r"(b[0]), "r"(b[1]));
}

// =======================================================================
// Kernel 0: gather + split conversion (once, outside the GEMM hot loop)
// =======================================================================
__global__ __launch_bounds__(256) void preconv_kernel(
    const int* __restrict__ doc,
    const float* __restrict__ emb,
    const float* __restrict__ diags)
{
    const int idx = blockIdx.x * 256 + threadIdx.x;
    const int totalA = 2048 * KSLOT;
    const int totalB = BROWS * KSLOT;
    float4 v = make_float4(0.f, 0.f, 0.f, 0.f);
    if (idx < totalA) {
        int row = idx / KSLOT, s = idx - row * KSLOT, k = s * 4;
        if (k < 300) v = *(const float4*)(emb + (size_t)doc[row] * 300 + k);
        unsigned h01, m01, h23, m23;
        bsplit2(v.x, v.y, h01, m01);
        bsplit2(v.z, v.w, h23, m23);
        g_Apre[idx] = make_uint4(h01, m01, h23, m23);
    } else if (idx < totalA + totalB) {
        int j = idx - totalA;
        int row = j / KSLOT, s = j - row * KSLOT, k = s * 4;
        if (k < 300 && row < D_COLS)
            v = *(const float4*)(diags + (size_t)row * 300 + k);
        unsigned h01, m01, h23, m23;
        bsplit2(v.x, v.y, h01, m01);
        bsplit2(v.z, v.w, h23, m23);
        g_Bpre[j] = make_uint4(h01, m01, h23, m23);
    }
}

// =======================================================================
// Kernel 1: GEMM via mma.sync on pre-split bf16 + bias + sigmoid
//   CTA 64x96, BK=16, 19 stages, 8 warps (2m x 4n), warp tile 32x24.
// =======================================================================
#define BM 64
#define BN 96
#define NTW 3
#define NKS 19
#define RSTRIDE 24                   // smem row stride in u32 (96B): LDS.64 conflict-free
#define ABUFU32 (BM * RSTRIDE)       // 1536 u32
#define BBUFU32 (BN * RSTRIDE)       // 2304 u32
#define STAGEU32 (ABUFU32 + BBUFU32) // 3840 u32
#define SMEM_BYTES (2 * STAGEU32 * 4) // 30720 B

__global__ __launch_bounds__(256, 3) void gemm_mma_kernel(
    const float* __restrict__ bias)
{
    extern __shared__ unsigned sm[];
    unsigned* Abuf[2] = { sm,               sm + STAGEU32 };
    unsigned* Bbuf[2] = { sm + ABUFU32,     sm + STAGEU32 + ABUFU32 };

    const int tid = threadIdx.x;
    const int wid = tid >> 5;
    const int lane = tid & 31;
    const int wmh = wid >> 2;
    const int wn = wid & 3;
    const int grp = lane >> 2;
    const int tig = lane & 3;
    const int n0 = blockIdx.x * BN;
    const int m0 = blockIdx.y * BM;

    float acc[2][NTW][4];
#pragma unroll
    for (int i = 0; i < 2; i++)
#pragma unroll
        for (int j = 0; j < NTW; j++)
#pragma unroll
            for (int r = 0; r < 4; r++) acc[i][j][r] = 0.0f;

    const int rowT = tid >> 2;
    const int slot = tid & 3;
    const bool hasB1 = tid < 128;
    const uint4* pA  = g_Apre + (size_t)(m0 + rowT) * KSLOT + slot;
    const uint4* pB0 = g_Bpre + (size_t)(n0 + rowT) * KSLOT + slot;
    const uint4* pB1 = g_Bpre + (size_t)(n0 + (hasB1 ? 64 + rowT : rowT)) * KSLOT + slot;

    const int sA  = rowT * RSTRIDE + slot * 4;
    const int sB0 = rowT * RSTRIDE + slot * 4;
    const int sB1 = (64 + rowT) * RSTRIDE + slot * 4;

    uint4 ra4  = pA[0];
    uint4 rb40 = pB0[0];
    uint4 rb41 = hasB1 ? pB1[0] : make_uint4(0u, 0u, 0u, 0u);
    pA += 4; pB0 += 4; pB1 += 4;
    *(uint4*)(Abuf[0] + sA)  = ra4;
    *(uint4*)(Bbuf[0] + sB0) = rb40;
    if (hasB1) *(uint4*)(Bbuf[0] + sB1) = rb41;
    __syncthreads();

    for (int c = 0; c < NKS; c++) {
        if (c + 1 < NKS) {
            ra4  = pA[0];
            rb40 = pB0[0];
            if (hasB1) rb41 = pB1[0];
            pA += 4; pB0 += 4; pB1 += 4;
        }
        {
            const unsigned* As = Abuf[c & 1];
            const unsigned* Bs = Bbuf[c & 1];
            unsigned bh[NTW][2], bm[NTW][2];
#pragma unroll
            for (int nt = 0; nt < NTW; nt++) {
                const unsigned* p = Bs + (wn * 24 + nt * 8 + grp) * RSTRIDE + tig * 2;
                uint2 v0 = *(const uint2*)p;
                uint2 v1 = *(const uint2*)(p + 8);
                bh[nt][0] = v0.x; bm[nt][0] = v0.y;
                bh[nt][1] = v1.x; bm[nt][1] = v1.y;
            }
#pragma unroll
            for (int mt = 0; mt < 2; mt++) {
                const unsigned* p = As + (wmh * 32 + mt * 16 + grp) * RSTRIDE + tig * 2;
                uint2 a0 = *(const uint2*)p;
                uint2 a1 = *(const uint2*)(p + 8 * RSTRIDE);
                uint2 a2 = *(const uint2*)(p + 8);
                uint2 a3 = *(const uint2*)(p + 8 * RSTRIDE + 8);
                unsigned ah[4] = { a0.x, a1.x, a2.x, a3.x };
                unsigned am[4] = { a0.y, a1.y, a2.y, a3.y };
#pragma unroll
                for (int nt = 0; nt < NTW; nt++) {
                    mma_bf16(acc[mt][nt], ah, bh[nt]);
                    mma_bf16(acc[mt][nt], am, bh[nt]);
                    mma_bf16(acc[mt][nt], ah, bm[nt]);
                }
            }
        }
        if (c + 1 < NKS) {
            unsigned* An = Abuf[(c + 1) & 1];
            unsigned* Bn = Bbuf[(c + 1) & 1];
            *(uint4*)(An + sA)  = ra4;
            *(uint4*)(Bn + sB0) = rb40;
            if (hasB1) *(uint4*)(Bn + sB1) = rb41;
        }
        __syncthreads();
    }

    // ---- epilogue: via smem (64 x 100), coalesced stores ----
    float* smep = (float*)sm;
#pragma unroll
    for (int mt = 0; mt < 2; mt++) {
        const int r0 = wmh * 32 + mt * 16 + grp;
#pragma unroll
        for (int nt = 0; nt < NTW; nt++) {
            const int cb = wn * 24 + nt * 8 + 2 * tig;
            smep[r0 * 100 + cb]           = acc[mt][nt][0];
            smep[r0 * 100 + cb + 1]       = acc[mt][nt][1];
            smep[(r0 + 8) * 100 + cb]     = acc[mt][nt][2];
            smep[(r0 + 8) * 100 + cb + 1] = acc[mt][nt][3];
        }
    }
    __syncthreads();
#pragma unroll
    for (int i = 0; i < 6; i++) {
        int slot2 = tid + i * 256;
        int r = slot2 / 24;
        int c4 = (slot2 % 24) * 4;
        int gn = n0 + c4;
        if (gn < D_COLS) {
            float4 bv = *(const float4*)(bias + gn);
            float4 o;
            o.x = 1.0f / (1.0f + __expf(-(smep[r * 100 + c4]     + bv.x)));
            o.y = 1.0f / (1.0f + __expf(-(smep[r * 100 + c4 + 1] + bv.y)));
            o.z = 1.0f / (1.0f + __expf(-(smep[r * 100 + c4 + 2] + bv.z)));
            o.w = 1.0f / (1.0f + __expf(-(smep[r * 100 + c4 + 3] + bv.w)));
            *(float4*)(g_tm + (size_t)(m0 + r) * D_COLS + gn) = o;
        }
    }
}

// =======================================================================
// Kernel 2: chunked parallel scan (CH=64, NCHUNK=32)
// =======================================================================
template <int P>
__device__ __forceinline__ void scan_impl(
    const float* __restrict__ eps_raw,
    float eps_sc, float sls,
    int groupStart, int scoreOff, int chunk)
{
    const int n = threadIdx.x;
    if (n >= 50) return;

    float eps[P - 1];
#pragma unroll
    for (int j = 0; j < P - 1; j++)
        eps[j] = eps_sc * sigmoidf(eps_raw[n * (P - 1) + j]);

    const float* base = g_tm + groupStart + n * 2 * P;

    const int acc_start = chunk * CH;
    int t_begin = acc_start - WARM;
    if (t_begin < 0) t_begin = 0;
    const int t_end = acc_start + CH;
    const int nsteps = t_end - t_begin;

    constexpr int DEPTH = 8;
    float2 buf[DEPTH][P];

#pragma unroll
    for (int d = 0; d < DEPTH; d++) {
        const float2* rp = (const float2*)(base + (size_t)(t_begin + d) * D_COLS);
#pragma unroll
        for (int j = 0; j < P; j++) buf[d][j] = rp[j];
    }

    float h[P];
    h[0] = 1.0f;
#pragma unroll
    for (int i = 1; i < P; i++) h[i] = 0.0f;
    float sc = 0.0f;

    for (int sb2 = 0; sb2 < nsteps; sb2 += DEPTH) {
#pragma unroll
        for (int d = 0; d < DEPTH; d++) {
            const int t = t_begin + sb2 + d;
            float v[2 * P];
#pragma unroll
            for (int j = 0; j < P; j++) {
                v[2 * j]     = buf[d][j].x;
                v[2 * j + 1] = buf[d][j].y;
            }
            const int tn = t + DEPTH;
            if (tn < t_end) {
                const float2* rp = (const float2*)(base + (size_t)tn * D_COLS);
#pragma unroll
                for (int j = 0; j < P; j++) buf[d][j] = rp[j];
            }
#pragma unroll
            for (int i = P - 1; i >= 1; --i)
                h[i] = fmaf(h[i - 1], eps[i - 1], h[i]);
            float res[P];
            res[0] = fmaf(sls * h[0], v[0], 1.0f);
#pragma unroll
            for (int i = 1; i < P; i++)
                res[i] = fmaf(h[i - 1], v[P + i - 1], sls * h[i] * v[i]);
            if (t >= acc_start) sc += res[P - 1];
#pragma unroll
            for (int i = 0; i < P; i++) h[i] = res[i];
        }
    }
    g_part[chunk * 300 + scoreOff + n] = sc;
}

__global__ __launch_bounds__(64) void scan_all_kernel(
    const float* e2, const float* e3, const float* e4,
    const float* e5, const float* e6, const float* e7,
    const float* __restrict__ eps_scale,
    const float* __restrict__ sls_scale)
{
    const float eps_sc = sigmoidf(eps_scale[0]);
    const float sls = sigmoidf(sls_scale[0]);
    const int chunk = blockIdx.y;
    switch (blockIdx.x) {
        case 0: scan_impl<2>(e2, eps_sc, sls,    0,   0, chunk); break;
        case 1: scan_impl<3>(e3, eps_sc, sls,  200,  50, chunk); break;
        case 2: scan_impl<4>(e4, eps_sc, sls,  500, 100, chunk); break;
        case 3: scan_impl<5>(e5, eps_sc, sls,  900, 150, chunk); break;
        case 4: scan_impl<6>(e6, eps_sc, sls, 1400, 200, chunk); break;
        case 5: scan_impl<7>(e7, eps_sc, sls, 2000, 250, chunk); break;
    }
}

// =======================================================================
// Kernel 3a: layer-1 partials across 25 blocks (12 patterns each).
//   512 threads = 128 k-lanes x 4 j-groups of 3 (constant bounds, fully
//   unrolled -> ptxas front-loads all 3 w1 loads per thread).
// =======================================================================
__global__ __launch_bounds__(512) void mlp_part_kernel(
    const float* __restrict__ w1)
{
    __shared__ float ssc[MLPJ];
    __shared__ float part[4][128];
    const int b = blockIdx.x;          // 0..24
    const int j0 = b * MLPJ;
    const int tid = threadIdx.x;

    // reduce this block's pattern slice: g_part[c][j0+tid], lanes coalesced
    if (tid < MLPJ) {
        float a = 0.0f;
        const float* gp = g_part + j0 + tid;
#pragma unroll
        for (int c = 0; c < NCHUNK; c++) a += gp[c * 300];
        ssc[tid] = a;
    }
    __syncthreads();

    const int k = tid & 127;           // 0..127 (k<100 active)
    const int jg = tid >> 7;           // 0..3 : j-group of 3
    float a = 0.0f;
    if (k < 100) {
        const int js = jg * 3;
#pragma unroll
        for (int j = 0; j < 3; j++)
            a = fmaf(ssc[js + j], w1[(j0 + js + j) * 100 + k], a);
    }
    part[jg][k] = a;
    __syncthreads();
    if (tid < 100)
        g_hpart[b * 100 + tid] = part[0][tid] + part[1][tid]
                               + part[2][tid] + part[3][tid];
}

// =======================================================================
// Kernel 3b: combine 25 partial groups + relu + layer 2
// =======================================================================
__global__ __launch_bounds__(128) void mlp_final_kernel(
    const float* __restrict__ b1,
    const float* __restrict__ w2, const float* __restrict__ b2,
    float* __restrict__ out)
{
    __shared__ float hsh[100];
    const int tid = threadIdx.x;
    if (tid < 100) {
        float h = b1[tid];
#pragma unroll
        for (int g = 0; g < MLPB; g++) h += g_hpart[g * 100 + tid];
        hsh[tid] = fmaxf(h, 0.0f);
    }
    __syncthreads();
    if (tid < 64) {
        const int c = tid >> 5;
        const int l = tid & 31;
        float o = 0.0f;
        for (int i = l; i < 100; i += 32)
            o = fmaf(hsh[i], w2[i * 2 + c], o);
#pragma unroll
        for (int s = 16; s > 0; s >>= 1)
            o += __shfl_xor_sync(0xffffffffu, o, s);
        if (l == 0) out[c] = o + b2[c];
    }
}

// ---------------- Launch ----------------
extern "C" void kernel_launch(void* const* d_in, const int* in_sizes, int n_in,
                              void* d_out, int out_size)
{
    const int*   doc       = (const int*)  d_in[0];
    const float* emb       = (const float*)d_in[1];
    const float* diags     = (const float*)d_in[2];
    const float* bias      = (const float*)d_in[3];
    const float* e2        = (const float*)d_in[4];
    const float* e3        = (const float*)d_in[5];
    const float* e4        = (const float*)d_in[6];
    const float* e5        = (const float*)d_in[7];
    const float* e6        = (const float*)d_in[8];
    const float* e7        = (const float*)d_in[9];
    const float* eps_scale = (const float*)d_in[10];
    const float* sls_scale = (const float*)d_in[11];
    const float* w1        = (const float*)d_in[12];
    const float* b1        = (const float*)d_in[13];
    const float* w2        = (const float*)d_in[14];
    const float* b2        = (const float*)d_in[15];
    float* out = (float*)d_out;

    const int totalPre = 2048 * KSLOT + BROWS * KSLOT;
    preconv_kernel<<<(totalPre + 255) / 256, 256>>>(doc, emb, diags);
    gemm_mma_kernel<<<dim3((D_COLS + BN - 1) / BN, T_LEN / BM), 256, SMEM_BYTES>>>(bias);
    scan_all_kernel<<<dim3(6, NCHUNK), 64>>>(e2, e3, e4, e5, e6, e7, eps_scale, sls_scale);
    mlp_part_kernel<<<MLPB, 512>>>(w1);
    mlp_final_kernel<<<1, 128>>>(b1, w2, b2, out);
}